// round 12
// baseline (speedup 1.0000x reference)
#include <cuda_runtime.h>
#include <cuda_bf16.h>
#include <cuda_fp16.h>
#include <cstdint>
#include <math.h>

// ---------------------------------------------------------------------------
// Problem constants
// ---------------------------------------------------------------------------
#define NN 50000      // nodes per type
#define EE 200000     // edges per relation
// REL = [(0,1),(1,0),(0,0),(1,1)]
#define NC 640        // fused projection width: [K_rA | K_rB | V_rA | V_rB | Q]
#define NCW 320       // bf16-packed row width in 32-bit words

// ---------------------------------------------------------------------------
// Scratch layout (32-bit words)
// ---------------------------------------------------------------------------
constexpr size_t OFF_C0    = 0;                                  // NN*320 (bf16x2)
constexpr size_t OFF_C1    = OFF_C0    + (size_t)NN * NCW;
constexpr size_t OFF_N16   = OFF_C1    + (size_t)NN * NCW;       // 4*NN*64 (f16x2 words)
constexpr size_t OFF_DEN   = OFF_N16   + (size_t)4 * NN * 64;    // 4*NN*8 fp32
constexpr size_t OFF_AGGH  = OFF_DEN   + (size_t)4 * NN * 8;     // 2*NN*64 bf16x2
constexpr size_t OFF_AGGL  = OFF_AGGH  + (size_t)2 * NN * 64;
constexpr size_t OFF_XH    = OFF_AGGL  + (size_t)2 * NN * 64;    // 2*NN*64
constexpr size_t OFF_XL    = OFF_XH    + (size_t)2 * NN * 64;
constexpr size_t OFF_WCAT  = OFF_XL    + (size_t)2 * NN * 64;    // 2*128*640 fp32
constexpr size_t OFF_BCAT  = OFF_WCAT  + (size_t)2 * 128 * NC;   // 2*640 fp32
constexpr size_t OFF_WH    = OFF_BCAT  + (size_t)2 * NC;         // 2*64*640
constexpr size_t OFF_WL    = OFF_WH    + (size_t)2 * 64 * NC;
constexpr size_t OFF_WAH   = OFF_WL    + (size_t)2 * 64 * NC;    // 2*64*128
constexpr size_t OFF_WAL   = OFF_WAH   + (size_t)2 * 64 * 128;
constexpr size_t BUF_TOTAL = OFF_WAL   + (size_t)2 * 64 * 128;

__device__ float g_buf[BUF_TOTAL];

// ---------------------------------------------------------------------------
// helpers
// ---------------------------------------------------------------------------
__device__ __forceinline__ uint32_t pack_bf16x2(float x, float y) {
    uint32_t r;
    asm("cvt.rn.bf16x2.f32 %0, %1, %2;" : "=r"(r) : "f"(y), "f"(x));
    return r;
}
__device__ __forceinline__ uint32_t pack_f16x2(float x, float y) {
    uint32_t r;
    asm("cvt.rn.f16x2.f32 %0, %1, %2;" : "=r"(r) : "f"(y), "f"(x));
    return r;
}
__device__ __forceinline__ float lo_as_f32(uint32_t p) { return __uint_as_float(p << 16); }
__device__ __forceinline__ float hi_as_f32(uint32_t p) { return __uint_as_float(p & 0xffff0000u); }

__device__ __forceinline__ void mma_bf16(float* c, const uint32_t* a, const uint32_t* b) {
    asm volatile(
        "mma.sync.aligned.m16n8k16.row.col.f32.bf16.bf16.f32 "
        "{%0,%1,%2,%3}, {%4,%5,%6,%7}, {%8,%9}, {%0,%1,%2,%3};"
        : "+f"(c[0]), "+f"(c[1]), "+f"(c[2]), "+f"(c[3])
        : "r"(a[0]), "r"(a[1]), "r"(a[2]), "r"(a[3]), "r"(b[0]), "r"(b[1]));
}

__device__ __forceinline__ void ldsm_x4(uint32_t* r, uint32_t addr) {
    asm volatile("ldmatrix.sync.aligned.m8n8.x4.shared.b16 {%0,%1,%2,%3}, [%4];"
                 : "=r"(r[0]), "=r"(r[1]), "=r"(r[2]), "=r"(r[3]) : "r"(addr));
}

__device__ __forceinline__ void cp_async16(uint32_t dst, const void* src, int srcbytes) {
    asm volatile("cp.async.cg.shared.global [%0], [%1], 16, %2;"
                 :: "r"(dst), "l"(src), "r"(srcbytes) : "memory");
}

__host__ __device__ __forceinline__ int wperm(int n) {
    return (n & ~63) | (((n & 7) << 3) | ((n >> 3) & 7));
}

// ---------------------------------------------------------------------------
// 3xBF16 tensor-core GEMM (round-8 proven version) — projections only
// ---------------------------------------------------------------------------
#define BM 128
#define BN 64
#define APITCH 20
#define A_STG (BM * APITCH)
#define W_STG (16 * 72)
#define GSMEM_WORDS (4 * A_STG + 4 * W_STG)
#define GSMEM_BYTES (GSMEM_WORDS * 4)

__global__ __launch_bounds__(256, 2) void gemm3p(const uint32_t* __restrict__ AH,
                                                 const uint32_t* __restrict__ AL,
                                                 const uint32_t* __restrict__ WH,
                                                 const uint32_t* __restrict__ WL,
                                                 int ldww,
                                                 const float* __restrict__ bias,
                                                 uint32_t* __restrict__ Cw, int ldcw,
                                                 int M) {
    extern __shared__ uint32_t sm[];
    uint32_t smbase = (uint32_t)__cvta_generic_to_shared(sm);

    int tid  = threadIdx.x;
    int warp = tid >> 5;
    int lane = tid & 31;
    int g    = lane >> 2;
    int t4   = lane & 3;
    int warpM = warp >> 1;
    int warpN = warp & 1;

    int m0 = blockIdx.x * BM;
    int n0 = blockIdx.y * BN;

    int lrow  = lane & 15;
    int lcolw = (lane >> 4) * 4;

    float acc[2][4][4];
#pragma unroll
    for (int i = 0; i < 2; i++)
#pragma unroll
        for (int j = 0; j < 4; j++)
#pragma unroll
            for (int k = 0; k < 4; k++) acc[i][j][k] = 0.f;

    auto stage_load = [&](int s, int kb) {
        int kb2 = kb >> 1;
#pragma unroll
        for (int i = 0; i < 2; i++) {
            int c   = i * 256 + tid;
            int row = c >> 2;
            int cw  = (c & 3) * 4;
            int m   = m0 + row;
            int ok  = (m < M) ? 16 : 0;
            size_t srcoff = (size_t)(m < M ? m : M - 1) * 64 + kb2 + cw;
            uint32_t dH = smbase + (uint32_t)((s * A_STG + row * APITCH + cw) * 4);
            uint32_t dL = smbase + (uint32_t)(((2 + s) * A_STG + row * APITCH + cw) * 4);
            cp_async16(dH, AH + srcoff, ok);
            cp_async16(dL, AL + srcoff, ok);
        }
        {
            int pk = tid >> 4;
            int cg = tid & 15;
            size_t srcoff = (size_t)(kb2 + pk) * ldww + n0 + cg * 4;
            uint32_t dH = smbase + (uint32_t)((4 * A_STG + s * W_STG + pk * 72 + cg * 4) * 4);
            uint32_t dL = smbase + (uint32_t)((4 * A_STG + (2 + s) * W_STG + pk * 72 + cg * 4) * 4);
            cp_async16(dH, WH + srcoff, 16);
            cp_async16(dL, WL + srcoff, 16);
        }
        asm volatile("cp.async.commit_group;" ::: "memory");
    };

    stage_load(0, 0);

    int s = 0;
    for (int kb = 0; kb < 128; kb += 32, s ^= 1) {
        if (kb + 32 < 128) {
            stage_load(s ^ 1, kb + 32);
            asm volatile("cp.async.wait_group 1;" ::: "memory");
        } else {
            asm volatile("cp.async.wait_group 0;" ::: "memory");
        }
        __syncthreads();

        uint32_t asHs = smbase + (uint32_t)(s * A_STG * 4);
        uint32_t asLs = smbase + (uint32_t)((2 + s) * A_STG * 4);
        const uint32_t* wsH = sm + 4 * A_STG + s * W_STG;
        const uint32_t* wsL = sm + 4 * A_STG + (2 + s) * W_STG;

#pragma unroll
        for (int ks = 0; ks < 2; ks++) {
            int kp = ks * 8;
            uint32_t ah[2][4], al[2][4];
#pragma unroll
            for (int mt = 0; mt < 2; mt++) {
                int rb = warpM * 32 + mt * 16;
                uint32_t off = (uint32_t)(((rb + lrow) * APITCH + kp + lcolw) * 4);
                ldsm_x4(ah[mt], asHs + off);
                ldsm_x4(al[mt], asLs + off);
            }
            int colw = g * 8 + warpN * 4;
            uint4 bh0 = *(const uint4*)&wsH[(kp + t4) * 72 + colw];
            uint4 bh1 = *(const uint4*)&wsH[(kp + t4 + 4) * 72 + colw];
            uint4 bl0 = *(const uint4*)&wsL[(kp + t4) * 72 + colw];
            uint4 bl1 = *(const uint4*)&wsL[(kp + t4 + 4) * 72 + colw];
            const uint32_t* ph0 = (const uint32_t*)&bh0;
            const uint32_t* ph1 = (const uint32_t*)&bh1;
            const uint32_t* pl0 = (const uint32_t*)&bl0;
            const uint32_t* pl1 = (const uint32_t*)&bl1;
#pragma unroll
            for (int nt = 0; nt < 4; nt++) {
                uint32_t bh[2] = {ph0[nt], ph1[nt]};
                uint32_t bl[2] = {pl0[nt], pl1[nt]};
#pragma unroll
                for (int mt = 0; mt < 2; mt++) {
                    mma_bf16(acc[mt][nt], ah[mt], bh);
                    mma_bf16(acc[mt][nt], ah[mt], bl);
                    mma_bf16(acc[mt][nt], al[mt], bh);
                }
            }
        }
        __syncthreads();
    }

#pragma unroll
    for (int mt = 0; mt < 2; mt++) {
#pragma unroll
        for (int nt = 0; nt < 4; nt++) {
            int col = n0 + warpN * 32 + nt * 8 + t4 * 2;
            float b0 = bias[col], b1 = bias[col + 1];
            int r0 = m0 + warpM * 32 + mt * 16 + g;
            int r1 = r0 + 8;
            if (r0 < M)
                Cw[(size_t)r0 * ldcw + (col >> 1)] = pack_bf16x2(acc[mt][nt][0] + b0, acc[mt][nt][1] + b1);
            if (r1 < M)
                Cw[(size_t)r1 * ldcw + (col >> 1)] = pack_bf16x2(acc[mt][nt][2] + b0, acc[mt][nt][3] + b1);
        }
    }
}

// ---------------------------------------------------------------------------
// Fused output GEMM + skip + LayerNorm.
// C = AGG[M,128] @ Wa[128,128] + ba ; x = a*C + (1-a)*h ; out = LN(x)*g + b
// 512 threads (16 warps, 4x4), BM=128, BN=128 (full rows per block).
// ---------------------------------------------------------------------------
#define W_STG2 (16 * 136)
#define GSMEM2_WORDS (4 * A_STG + 4 * W_STG2)
#define GSMEM2_BYTES (GSMEM2_WORDS * 4)

__global__ __launch_bounds__(512, 1) void gemm_out_ln(
    const uint32_t* __restrict__ AH, const uint32_t* __restrict__ AL,
    const uint32_t* __restrict__ WH, const uint32_t* __restrict__ WL,
    const float* __restrict__ bias,
    const float* __restrict__ hfeat,
    const float* __restrict__ skipp, int tsel,
    const float* __restrict__ lng, const float* __restrict__ lnb,
    float* __restrict__ out, int M) {
    extern __shared__ uint32_t sm[];
    __shared__ float2 red_sm[512];
    uint32_t smbase = (uint32_t)__cvta_generic_to_shared(sm);

    int tid  = threadIdx.x;
    int warp = tid >> 5;
    int lane = tid & 31;
    int g    = lane >> 2;
    int t4   = lane & 3;
    int warpM = warp >> 2;   // 0..3
    int warpN = warp & 3;    // 0..3

    int m0 = blockIdx.x * BM;

    int lrow  = lane & 15;
    int lcolw = (lane >> 4) * 4;

    float acc[2][4][4];
#pragma unroll
    for (int i = 0; i < 2; i++)
#pragma unroll
        for (int j = 0; j < 4; j++)
#pragma unroll
            for (int k = 0; k < 4; k++) acc[i][j][k] = 0.f;

    auto stage_load = [&](int s, int kb) {
        int kb2 = kb >> 1;
        {
            int row = tid >> 2;
            int cw  = (tid & 3) * 4;
            int m   = m0 + row;
            int ok  = (m < M) ? 16 : 0;
            size_t srcoff = (size_t)(m < M ? m : M - 1) * 64 + kb2 + cw;
            cp_async16(smbase + (uint32_t)((s * A_STG + row * APITCH + cw) * 4), AH + srcoff, ok);
            cp_async16(smbase + (uint32_t)(((2 + s) * A_STG + row * APITCH + cw) * 4), AL + srcoff, ok);
        }
        {
            int pk = tid >> 5;       // 0..15
            int cg = tid & 31;       // 0..31 (32 uint4 per 128-word row)
            size_t srcoff = (size_t)(kb2 + pk) * 128 + cg * 4;
            cp_async16(smbase + (uint32_t)((4 * A_STG + s * W_STG2 + pk * 136 + cg * 4) * 4), WH + srcoff, 16);
            cp_async16(smbase + (uint32_t)((4 * A_STG + (2 + s) * W_STG2 + pk * 136 + cg * 4) * 4), WL + srcoff, 16);
        }
        asm volatile("cp.async.commit_group;" ::: "memory");
    };

    stage_load(0, 0);

    int s = 0;
    for (int kb = 0; kb < 128; kb += 32, s ^= 1) {
        if (kb + 32 < 128) {
            stage_load(s ^ 1, kb + 32);
            asm volatile("cp.async.wait_group 1;" ::: "memory");
        } else {
            asm volatile("cp.async.wait_group 0;" ::: "memory");
        }
        __syncthreads();

        uint32_t asHs = smbase + (uint32_t)(s * A_STG * 4);
        uint32_t asLs = smbase + (uint32_t)((2 + s) * A_STG * 4);
        const uint32_t* wsH = sm + 4 * A_STG + s * W_STG2;
        const uint32_t* wsL = sm + 4 * A_STG + (2 + s) * W_STG2;

#pragma unroll
        for (int ks = 0; ks < 2; ks++) {
            int kp = ks * 8;
            uint32_t ah[2][4], al[2][4];
#pragma unroll
            for (int mt = 0; mt < 2; mt++) {
                int rb = warpM * 32 + mt * 16;
                uint32_t off = (uint32_t)(((rb + lrow) * APITCH + kp + lcolw) * 4);
                ldsm_x4(ah[mt], asHs + off);
                ldsm_x4(al[mt], asLs + off);
            }
            // permuted column words: cb = warpN*32 + nt*8 + g
            //   group = warpN>>1, in-group perm -> g*8 + (warpN&1)*4 + nt
            int colw = (warpN >> 1) * 64 + g * 8 + (warpN & 1) * 4;
            uint4 bh0 = *(const uint4*)&wsH[(kp + t4) * 136 + colw];
            uint4 bh1 = *(const uint4*)&wsH[(kp + t4 + 4) * 136 + colw];
            uint4 bl0 = *(const uint4*)&wsL[(kp + t4) * 136 + colw];
            uint4 bl1 = *(const uint4*)&wsL[(kp + t4 + 4) * 136 + colw];
            const uint32_t* ph0 = (const uint32_t*)&bh0;
            const uint32_t* ph1 = (const uint32_t*)&bh1;
            const uint32_t* pl0 = (const uint32_t*)&bl0;
            const uint32_t* pl1 = (const uint32_t*)&bl1;
#pragma unroll
            for (int nt = 0; nt < 4; nt++) {
                uint32_t bh[2] = {ph0[nt], ph1[nt]};
                uint32_t bl[2] = {pl0[nt], pl1[nt]};
#pragma unroll
                for (int mt = 0; mt < 2; mt++) {
                    mma_bf16(acc[mt][nt], ah[mt], bh);
                    mma_bf16(acc[mt][nt], ah[mt], bl);
                    mma_bf16(acc[mt][nt], al[mt], bh);
                }
            }
        }
        __syncthreads();
    }

    // ---- fused epilogue: bias + skip-mix + LayerNorm ----
    float alpha = 1.f / (1.f + __expf(-skipp[tsel]));
    float beta  = 1.f - alpha;

#pragma unroll
    for (int mt = 0; mt < 2; mt++) {
#pragma unroll
        for (int half = 0; half < 2; half++) {
            int row = m0 + warpM * 32 + mt * 16 + half * 8 + g;
            float s1 = 0.f, s2 = 0.f;
            if (row < M) {
#pragma unroll
                for (int nt = 0; nt < 4; nt++) {
                    int col = warpN * 32 + nt * 8 + t4 * 2;
                    float tr0 = acc[mt][nt][half * 2]     + bias[col];
                    float tr1 = acc[mt][nt][half * 2 + 1] + bias[col + 1];
                    float2 hv = *(const float2*)&hfeat[(size_t)row * 128 + col];
                    float x0 = alpha * tr0 + beta * hv.x;
                    float x1 = alpha * tr1 + beta * hv.y;
                    acc[mt][nt][half * 2]     = x0;
                    acc[mt][nt][half * 2 + 1] = x1;
                    s1 += x0 + x1;
                    s2 += x0 * x0 + x1 * x1;
                }
            }
            // quad reduce (lanes within the same g-group)
            s1 += __shfl_xor_sync(0xffffffffu, s1, 1);
            s2 += __shfl_xor_sync(0xffffffffu, s2, 1);
            s1 += __shfl_xor_sync(0xffffffffu, s1, 2);
            s2 += __shfl_xor_sync(0xffffffffu, s2, 2);
            if (t4 == 0) {
                int rowslot = ((warpM * 2 + mt) * 2 + half) * 8 + g;
                red_sm[rowslot * 4 + warpN] = make_float2(s1, s2);
            }
        }
    }
    __syncthreads();

#pragma unroll
    for (int mt = 0; mt < 2; mt++) {
#pragma unroll
        for (int half = 0; half < 2; half++) {
            int row = m0 + warpM * 32 + mt * 16 + half * 8 + g;
            int rowslot = ((warpM * 2 + mt) * 2 + half) * 8 + g;
            float S1 = 0.f, S2 = 0.f;
#pragma unroll
            for (int w = 0; w < 4; w++) {
                float2 v = red_sm[rowslot * 4 + w];
                S1 += v.x; S2 += v.y;
            }
            float mean = S1 * (1.f / 128.f);
            float var  = S2 * (1.f / 128.f) - mean * mean;
            float rstd = rsqrtf(var + 1e-5f);
            if (row < M) {
#pragma unroll
                for (int nt = 0; nt < 4; nt++) {
                    int col = warpN * 32 + nt * 8 + t4 * 2;
                    float2 gg = *(const float2*)&lng[col];
                    float2 bb = *(const float2*)&lnb[col];
                    float x0 = acc[mt][nt][half * 2];
                    float x1 = acc[mt][nt][half * 2 + 1];
                    float2 o;
                    o.x = (x0 - mean) * rstd * gg.x + bb.x;
                    o.y = (x1 - mean) * rstd * gg.y + bb.y;
                    *(float2*)&out[(size_t)row * 128 + col] = o;
                }
            }
        }
    }
}

// ---------------------------------------------------------------------------
// Weight prep (unchanged)
// ---------------------------------------------------------------------------
__global__ void prep_wcat(const float* __restrict__ Wk, const float* __restrict__ bk,
                          const float* __restrict__ Wq, const float* __restrict__ bq,
                          const float* __restrict__ Wv, const float* __restrict__ bv,
                          const float* __restrict__ rel_att, const float* __restrict__ rel_msg) {
    int idx = blockIdx.x * blockDim.x + threadIdx.x;
    if (idx >= 2 * 128 * NC) return;
    int t = idx / (128 * NC);
    int i = (idx / NC) & 127;
    int c = idx % NC;

    float val, bval = 0.f;
    if (c < 512) {
        int sel = c >> 7;
        int rel = (sel & 1) ? (t == 0 ? 2 : 3) : (t == 0 ? 0 : 1);
        int isV = sel >> 1;
        int o = c & 127, h = o >> 4, eo = o & 15;
        const float* Wsrc = (isV ? Wv : Wk) + (size_t)t * 16384 + (size_t)i * 128 + h * 16;
        const float* bsrc = (isV ? bv : bk) + t * 128 + h * 16;
        const float* R = (isV ? rel_msg : rel_att) + (((size_t)rel * 8 + h) * 16) * 16 + eo;
        float a = 0.f, b = 0.f;
#pragma unroll
        for (int d = 0; d < 16; d++) {
            a += Wsrc[d] * R[d * 16];
            b += bsrc[d] * R[d * 16];
        }
        val = a; bval = b;
    } else {
        int o = c - 512;
        val = Wq[(size_t)t * 16384 + (size_t)i * 128 + o];
        bval = bq[t * 128 + o];
    }
    g_buf[OFF_WCAT + (size_t)t * 128 * NC + (size_t)i * NC + c] = val;
    if (i == 0) g_buf[OFF_BCAT + t * NC + c] = bval;
}

__global__ void pack_weights(const float* __restrict__ Wa) {
    uint32_t* W32 = (uint32_t*)g_buf;
    int idx = blockIdx.x * blockDim.x + threadIdx.x;
    int n_cat = 2 * 64 * NC;
    int n_wa  = 2 * 64 * 128;
    if (idx < n_cat) {
        int t  = idx / (64 * NC);
        int pk = (idx / NC) & 63;
        int n  = idx % NC;
        const float* Wt = g_buf + OFF_WCAT + (size_t)t * 128 * NC;
        float w0 = Wt[(size_t)(2 * pk)     * NC + n];
        float w1 = Wt[(size_t)(2 * pk + 1) * NC + n];
        uint32_t h = pack_bf16x2(w0, w1);
        uint32_t l = pack_bf16x2(w0 - lo_as_f32(h), w1 - hi_as_f32(h));
        int p = wperm(n);
        W32[OFF_WH + (size_t)t * 64 * NC + (size_t)pk * NC + p] = h;
        W32[OFF_WL + (size_t)t * 64 * NC + (size_t)pk * NC + p] = l;
    } else if (idx < n_cat + n_wa) {
        int j  = idx - n_cat;
        int t  = j / (64 * 128);
        int pk = (j / 128) & 63;
        int n  = j % 128;
        float w0 = Wa[(size_t)t * 16384 + (size_t)(2 * pk)     * 128 + n];
        float w1 = Wa[(size_t)t * 16384 + (size_t)(2 * pk + 1) * 128 + n];
        uint32_t h = pack_bf16x2(w0, w1);
        uint32_t l = pack_bf16x2(w0 - lo_as_f32(h), w1 - hi_as_f32(h));
        int p = wperm(n);
        W32[OFF_WAH + (size_t)t * 64 * 128 + (size_t)pk * 128 + p] = h;
        W32[OFF_WAL + (size_t)t * 64 * 128 + (size_t)pk * 128 + p] = l;
    }
}

__global__ void pack_x(const float* __restrict__ h0, const float* __restrict__ h1) {
    uint32_t* W32 = (uint32_t*)g_buf;
    int idx = blockIdx.x * blockDim.x + threadIdx.x;
    int total = 2 * NN * 64;
    if (idx >= total) return;
    int t = idx / (NN * 64);
    int rem = idx - t * (NN * 64);
    const float* h = t ? h1 : h0;
    float2 v = *(const float2*)&h[(size_t)rem * 2];
    uint32_t hi = pack_bf16x2(v.x, v.y);
    uint32_t lo = pack_bf16x2(v.x - lo_as_f32(hi), v.y - hi_as_f32(hi));
    W32[OFF_XH + (size_t)t * NN * 64 + rem] = hi;
    W32[OFF_XL + (size_t)t * NN * 64 + rem] = lo;
}

// ---------------------------------------------------------------------------
// Zero N16 (f16x2 numerator) and DEN — contiguous; uint4 stores
// ---------------------------------------------------------------------------
__global__ void zero_accum() {
    uint4* p = (uint4*)(g_buf + OFF_N16);
    size_t n4 = ((size_t)4 * NN * 64 + (size_t)4 * NN * 8) / 4;
    size_t i = (size_t)blockIdx.x * blockDim.x + threadIdx.x;
    size_t stride = (size_t)gridDim.x * blockDim.x;
    uint4 z = make_uint4(0, 0, 0, 0);
    for (; i < n4; i += stride) p[i] = z;
}

// ---------------------------------------------------------------------------
// Single edge pass over bf16 projections. One warp per edge.
// Numerator accumulated via f16x2 RED.
// ---------------------------------------------------------------------------
__global__ void edge_pass(const float* __restrict__ pri,
                          const int* __restrict__ s0, const int* __restrict__ d0,
                          const int* __restrict__ s1, const int* __restrict__ d1,
                          const int* __restrict__ s2, const int* __restrict__ d2,
                          const int* __restrict__ s3, const int* __restrict__ d3) {
    int r = blockIdx.y;
    int e = blockIdx.x * (blockDim.x >> 5) + (threadIdx.x >> 5);
    if (e >= EE) return;
    int lane = threadIdx.x & 31;

    const int* src = (r == 0) ? s0 : (r == 1) ? s1 : (r == 2) ? s2 : s3;
    const int* dst = (r == 0) ? d0 : (r == 1) ? d1 : (r == 2) ? d2 : d3;
    int st = r & 1;
    int dt = (r == 0 || r == 3) ? 1 : 0;
    int sliceKVw = (r >> 1) * 64;

    int s = src[e];
    int d = dst[e];

    const uint32_t* Cw = (const uint32_t*)g_buf;
    const uint32_t* Cs = Cw + (st ? OFF_C1 : OFF_C0) + (size_t)s * NCW;
    const uint32_t* Cd = Cw + (dt ? OFF_C1 : OFF_C0) + (size_t)d * NCW;

    uint2 qw = *(const uint2*)&Cd[256 + lane * 2];
    uint2 kw = *(const uint2*)&Cs[sliceKVw + lane * 2];
    float p = lo_as_f32(qw.x) * lo_as_f32(kw.x) + hi_as_f32(qw.x) * hi_as_f32(kw.x)
            + lo_as_f32(qw.y) * lo_as_f32(kw.y) + hi_as_f32(qw.y) * hi_as_f32(kw.y);
    p += __shfl_xor_sync(0xffffffffu, p, 1);
    p += __shfl_xor_sync(0xffffffffu, p, 2);
    int h = lane >> 2;
    float sc = p * pri[r * 8 + h] * 0.25f;
    float ex = __expf(sc);

    if ((lane & 3) == 0) {
        float* dp = g_buf + OFF_DEN + ((size_t)r * NN + d) * 8 + h;
        asm volatile("red.global.add.f32 [%0], %1;" :: "l"(dp), "f"(ex) : "memory");
    }

    uint2 vw = *(const uint2*)&Cs[128 + sliceKVw + lane * 2];
    float p0 = lo_as_f32(vw.x) * ex, p1 = hi_as_f32(vw.x) * ex;
    float p2 = lo_as_f32(vw.y) * ex, p3 = hi_as_f32(vw.y) * ex;
    uint32_t w0 = pack_f16x2(p0, p1);
    uint32_t w1 = pack_f16x2(p2, p3);
    uint32_t* np = (uint32_t*)g_buf + OFF_N16 + ((size_t)r * NN + d) * 64 + lane * 2;
    asm volatile("red.global.add.noftz.f16x2 [%0], %1;" :: "l"(np),     "r"(w0) : "memory");
    asm volatile("red.global.add.noftz.f16x2 [%0], %1;" :: "l"(np + 1), "r"(w1) : "memory");
}

// ---------------------------------------------------------------------------
// Normalize + cross-relation mean; reads f16x2 numerator; emits packed bf16
// hi/lo AGG images
// ---------------------------------------------------------------------------
__global__ void agg_pack() {
    uint32_t* W32 = (uint32_t*)g_buf;
    const uint32_t* N16 = (const uint32_t*)g_buf + OFF_N16;
    size_t total = (size_t)2 * NN * 64;
    size_t i = (size_t)blockIdx.x * blockDim.x + threadIdx.x;
    size_t stride = (size_t)gridDim.x * blockDim.x;
    for (; i < total; i += stride) {
        int w = (int)(i & 63);
        size_t nt = i >> 6;
        int t = (int)(nt / NN);
        int n = (int)(nt % NN);
        int rA = (t == 0) ? 1 : 0;
        int rB = (t == 0) ? 2 : 3;
        int h = w >> 3;
        float dA = g_buf[OFF_DEN + ((size_t)rA * NN + n) * 8 + h];
        float dB = g_buf[OFF_DEN + ((size_t)rB * NN + n) * 8 + h];
        float iA = (dA > 0.f) ? 0.5f / dA : 0.f;
        float iB = (dB > 0.f) ? 0.5f / dB : 0.f;
        uint32_t wA = N16[((size_t)rA * NN + n) * 64 + w];
        uint32_t wB = N16[((size_t)rB * NN + n) * 64 + w];
        float2 fA = __half22float2(*(const __half2*)&wA);
        float2 fB = __half22float2(*(const __half2*)&wB);
        float a0 = fA.x * iA + fB.x * iB;
        float a1 = fA.y * iA + fB.y * iB;
        uint32_t hi = pack_bf16x2(a0, a1);
        uint32_t lo = pack_bf16x2(a0 - lo_as_f32(hi), a1 - hi_as_f32(hi));
        W32[OFF_AGGH + i] = hi;
        W32[OFF_AGGL + i] = lo;
    }
}

// ---------------------------------------------------------------------------
// Host launcher
// ---------------------------------------------------------------------------
extern "C" void kernel_launch(void* const* d_in, const int* in_sizes, int n_in,
                              void* d_out, int out_size) {
    const float* h0 = (const float*)d_in[0];
    const float* h1 = (const float*)d_in[1];
    const int* s0 = (const int*)d_in[2];
    const int* d0 = (const int*)d_in[3];
    const int* s1 = (const int*)d_in[4];
    const int* d1 = (const int*)d_in[5];
    const int* s2 = (const int*)d_in[6];
    const int* d2 = (const int*)d_in[7];
    const int* s3 = (const int*)d_in[8];
    const int* d3 = (const int*)d_in[9];
    const float* Wk = (const float*)d_in[10];
    const float* bk = (const float*)d_in[11];
    const float* Wq = (const float*)d_in[12];
    const float* bq = (const float*)d_in[13];
    const float* Wv = (const float*)d_in[14];
    const float* bv = (const float*)d_in[15];
    const float* Wa = (const float*)d_in[16];
    const float* ba = (const float*)d_in[17];
    const float* rel_att = (const float*)d_in[18];
    const float* rel_msg = (const float*)d_in[19];
    const float* rel_pri = (const float*)d_in[20];
    const float* skip = (const float*)d_in[21];
    const float* ln_g = (const float*)d_in[22];
    const float* ln_b = (const float*)d_in[23];

    static float* buf = nullptr;
    if (!buf) {
        cudaGetSymbolAddress((void**)&buf, g_buf);
        cudaFuncSetAttribute(gemm3p,     cudaFuncAttributeMaxDynamicSharedMemorySize, GSMEM_BYTES);
        cudaFuncSetAttribute(gemm_out_ln, cudaFuncAttributeMaxDynamicSharedMemorySize, GSMEM2_BYTES);
    }
    uint32_t* buf32 = (uint32_t*)buf;

    // 1) weight prep + feature pack + accumulator zero
    prep_wcat<<<(2 * 128 * NC + 255) / 256, 256>>>(Wk, bk, Wq, bq, Wv, bv, rel_att, rel_msg);
    pack_weights<<<(2 * 64 * NC + 2 * 64 * 128 + 255) / 256, 256>>>(Wa);
    pack_x<<<(2 * NN * 64 + 255) / 256, 256>>>(h0, h1);
    zero_accum<<<1024, 256>>>();

    // 2) fused KVQ projections: per type, [NN,128] x [128,640] -> bf16 packed
    int mblocks = (NN + BM - 1) / BM;
    for (int t = 0; t < 2; t++) {
        dim3 gg(mblocks, NC / BN);
        gemm3p<<<gg, 256, GSMEM_BYTES>>>(
            buf32 + OFF_XH + (size_t)t * NN * 64,
            buf32 + OFF_XL + (size_t)t * NN * 64,
            buf32 + OFF_WH + (size_t)t * 64 * NC,
            buf32 + OFF_WL + (size_t)t * 64 * NC, NC,
            buf + OFF_BCAT + t * NC,
            buf32 + (t ? OFF_C1 : OFF_C0), NCW, NN);
    }

    // 3) single edge pass (all 4 relations; f16x2 numerator RED)
    dim3 gE((EE + 7) / 8, 4);
    edge_pass<<<gE, 256>>>(rel_pri, s0, d0, s1, d1, s2, d2, s3, d3);

    // 4) normalize + mean -> packed AGG images
    agg_pack<<<2048, 256>>>();

    // 5) fused output projection + skip + LayerNorm -> d_out
    const float* hs[2] = {h0, h1};
    for (int t = 0; t < 2; t++) {
        gemm_out_ln<<<mblocks, 512, GSMEM2_BYTES>>>(
            buf32 + OFF_AGGH + (size_t)t * NN * 64,
            buf32 + OFF_AGGL + (size_t)t * NN * 64,
            buf32 + OFF_WAH + (size_t)t * 64 * 128,
            buf32 + OFF_WAL + (size_t)t * 64 * 128,
            ba + t * 128,
            hs[t],
            skip, t,
            ln_g + t * 128, ln_b + t * 128,
            (float*)d_out + (size_t)t * NN * 128, NN);
    }
}

// round 14
// speedup vs baseline: 1.0276x; 1.0276x over previous
#include <cuda_runtime.h>
#include <cuda_bf16.h>
#include <cuda_fp16.h>
#include <cstdint>
#include <math.h>

// ---------------------------------------------------------------------------
// Problem constants
// ---------------------------------------------------------------------------
#define NN 50000      // nodes per type
#define EE 200000     // edges per relation
// REL = [(0,1),(1,0),(0,0),(1,1)]
#define NC 640        // fused projection width: [K_rA | K_rB | V_rA | V_rB | Q]
#define NCW 320       // bf16-packed row width in 32-bit words

// ---------------------------------------------------------------------------
// Scratch layout (32-bit words)
// ---------------------------------------------------------------------------
constexpr size_t OFF_C0    = 0;                                  // NN*320 (bf16x2)
constexpr size_t OFF_C1    = OFF_C0    + (size_t)NN * NCW;
constexpr size_t OFF_N16   = OFF_C1    + (size_t)NN * NCW;       // 4*NN*64 (f16x2 words)
constexpr size_t OFF_DEN   = OFF_N16   + (size_t)4 * NN * 64;    // 4*NN*8 fp32
constexpr size_t OFF_TRANS = OFF_DEN   + (size_t)4 * NN * 8;     // 2*NN*128 fp32
constexpr size_t OFF_AGGH  = OFF_TRANS + (size_t)2 * NN * 128;   // 2*NN*64 bf16x2
constexpr size_t OFF_AGGL  = OFF_AGGH  + (size_t)2 * NN * 64;
constexpr size_t OFF_XH    = OFF_AGGL  + (size_t)2 * NN * 64;    // 2*NN*64
constexpr size_t OFF_XL    = OFF_XH    + (size_t)2 * NN * 64;
constexpr size_t OFF_BCAT  = OFF_XL    + (size_t)2 * NN * 64;    // 2*640 fp32
constexpr size_t OFF_WH    = OFF_BCAT  + (size_t)2 * NC;         // 2*64*640
constexpr size_t OFF_WL    = OFF_WH    + (size_t)2 * 64 * NC;
constexpr size_t OFF_WAH   = OFF_WL    + (size_t)2 * 64 * NC;    // 2*64*128
constexpr size_t OFF_WAL   = OFF_WAH   + (size_t)2 * 64 * 128;
constexpr size_t BUF_TOTAL = OFF_WAL   + (size_t)2 * 64 * 128;

__device__ float g_buf[BUF_TOTAL];

// ---------------------------------------------------------------------------
// helpers
// ---------------------------------------------------------------------------
__device__ __forceinline__ uint32_t pack_bf16x2(float x, float y) {
    uint32_t r;
    asm("cvt.rn.bf16x2.f32 %0, %1, %2;" : "=r"(r) : "f"(y), "f"(x));
    return r;
}
__device__ __forceinline__ uint32_t pack_f16x2(float x, float y) {
    uint32_t r;
    asm("cvt.rn.f16x2.f32 %0, %1, %2;" : "=r"(r) : "f"(y), "f"(x));
    return r;
}
__device__ __forceinline__ float lo_as_f32(uint32_t p) { return __uint_as_float(p << 16); }
__device__ __forceinline__ float hi_as_f32(uint32_t p) { return __uint_as_float(p & 0xffff0000u); }

__device__ __forceinline__ void mma_bf16(float* c, const uint32_t* a, const uint32_t* b) {
    asm volatile(
        "mma.sync.aligned.m16n8k16.row.col.f32.bf16.bf16.f32 "
        "{%0,%1,%2,%3}, {%4,%5,%6,%7}, {%8,%9}, {%0,%1,%2,%3};"
        : "+f"(c[0]), "+f"(c[1]), "+f"(c[2]), "+f"(c[3])
        : "r"(a[0]), "r"(a[1]), "r"(a[2]), "r"(a[3]), "r"(b[0]), "r"(b[1]));
}

__device__ __forceinline__ void ldsm_x4(uint32_t* r, uint32_t addr) {
    asm volatile("ldmatrix.sync.aligned.m8n8.x4.shared.b16 {%0,%1,%2,%3}, [%4];"
                 : "=r"(r[0]), "=r"(r[1]), "=r"(r[2]), "=r"(r[3]) : "r"(addr));
}

__device__ __forceinline__ void cp_async16(uint32_t dst, const void* src, int srcbytes) {
    asm volatile("cp.async.cg.shared.global [%0], [%1], 16, %2;"
                 :: "r"(dst), "l"(src), "r"(srcbytes) : "memory");
}

__host__ __device__ __forceinline__ int wperm(int n) {
    return (n & ~63) | (((n & 7) << 3) | ((n >> 3) & 7));
}

// ---------------------------------------------------------------------------
// 3xBF16 tensor-core GEMM (round-8/11 proven version)
// ---------------------------------------------------------------------------
#define BM 128
#define BN 64
#define APITCH 20
#define A_STG (BM * APITCH)
#define W_STG (16 * 72)
#define GSMEM_WORDS (4 * A_STG + 4 * W_STG)
#define GSMEM_BYTES (GSMEM_WORDS * 4)

template<bool OUT_BF16>
__global__ __launch_bounds__(256, 2) void gemm3(const uint32_t* __restrict__ AH,
                                                const uint32_t* __restrict__ AL,
                                                const uint32_t* __restrict__ WH,
                                                const uint32_t* __restrict__ WL,
                                                int ldww,
                                                const float* __restrict__ bias,
                                                uint32_t* __restrict__ Cw, int ldcw,
                                                int M) {
    extern __shared__ uint32_t sm[];
    uint32_t smbase = (uint32_t)__cvta_generic_to_shared(sm);

    int tid  = threadIdx.x;
    int warp = tid >> 5;
    int lane = tid & 31;
    int g    = lane >> 2;
    int t4   = lane & 3;
    int warpM = warp >> 1;
    int warpN = warp & 1;

    int m0 = blockIdx.x * BM;
    int n0 = blockIdx.y * BN;

    int lrow  = lane & 15;
    int lcolw = (lane >> 4) * 4;

    float acc[2][4][4];
#pragma unroll
    for (int i = 0; i < 2; i++)
#pragma unroll
        for (int j = 0; j < 4; j++)
#pragma unroll
            for (int k = 0; k < 4; k++) acc[i][j][k] = 0.f;

    auto stage_load = [&](int s, int kb) {
        int kb2 = kb >> 1;
#pragma unroll
        for (int i = 0; i < 2; i++) {
            int c   = i * 256 + tid;
            int row = c >> 2;
            int cw  = (c & 3) * 4;
            int m   = m0 + row;
            int ok  = (m < M) ? 16 : 0;
            size_t srcoff = (size_t)(m < M ? m : M - 1) * 64 + kb2 + cw;
            uint32_t dH = smbase + (uint32_t)((s * A_STG + row * APITCH + cw) * 4);
            uint32_t dL = smbase + (uint32_t)(((2 + s) * A_STG + row * APITCH + cw) * 4);
            cp_async16(dH, AH + srcoff, ok);
            cp_async16(dL, AL + srcoff, ok);
        }
        {
            int pk = tid >> 4;
            int cg = tid & 15;
            size_t srcoff = (size_t)(kb2 + pk) * ldww + n0 + cg * 4;
            uint32_t dH = smbase + (uint32_t)((4 * A_STG + s * W_STG + pk * 72 + cg * 4) * 4);
            uint32_t dL = smbase + (uint32_t)((4 * A_STG + (2 + s) * W_STG + pk * 72 + cg * 4) * 4);
            cp_async16(dH, WH + srcoff, 16);
            cp_async16(dL, WL + srcoff, 16);
        }
        asm volatile("cp.async.commit_group;" ::: "memory");
    };

    stage_load(0, 0);

    int s = 0;
    for (int kb = 0; kb < 128; kb += 32, s ^= 1) {
        if (kb + 32 < 128) {
            stage_load(s ^ 1, kb + 32);
            asm volatile("cp.async.wait_group 1;" ::: "memory");
        } else {
            asm volatile("cp.async.wait_group 0;" ::: "memory");
        }
        __syncthreads();

        uint32_t asHs = smbase + (uint32_t)(s * A_STG * 4);
        uint32_t asLs = smbase + (uint32_t)((2 + s) * A_STG * 4);
        const uint32_t* wsH = sm + 4 * A_STG + s * W_STG;
        const uint32_t* wsL = sm + 4 * A_STG + (2 + s) * W_STG;

#pragma unroll
        for (int ks = 0; ks < 2; ks++) {
            int kp = ks * 8;
            uint32_t ah[2][4], al[2][4];
#pragma unroll
            for (int mt = 0; mt < 2; mt++) {
                int rb = warpM * 32 + mt * 16;
                uint32_t off = (uint32_t)(((rb + lrow) * APITCH + kp + lcolw) * 4);
                ldsm_x4(ah[mt], asHs + off);
                ldsm_x4(al[mt], asLs + off);
            }
            int colw = g * 8 + warpN * 4;
            uint4 bh0 = *(const uint4*)&wsH[(kp + t4) * 72 + colw];
            uint4 bh1 = *(const uint4*)&wsH[(kp + t4 + 4) * 72 + colw];
            uint4 bl0 = *(const uint4*)&wsL[(kp + t4) * 72 + colw];
            uint4 bl1 = *(const uint4*)&wsL[(kp + t4 + 4) * 72 + colw];
            const uint32_t* ph0 = (const uint32_t*)&bh0;
            const uint32_t* ph1 = (const uint32_t*)&bh1;
            const uint32_t* pl0 = (const uint32_t*)&bl0;
            const uint32_t* pl1 = (const uint32_t*)&bl1;
#pragma unroll
            for (int nt = 0; nt < 4; nt++) {
                uint32_t bh[2] = {ph0[nt], ph1[nt]};
                uint32_t bl[2] = {pl0[nt], pl1[nt]};
#pragma unroll
                for (int mt = 0; mt < 2; mt++) {
                    mma_bf16(acc[mt][nt], ah[mt], bh);
                    mma_bf16(acc[mt][nt], ah[mt], bl);
                    mma_bf16(acc[mt][nt], al[mt], bh);
                }
            }
        }
        __syncthreads();
    }

#pragma unroll
    for (int mt = 0; mt < 2; mt++) {
#pragma unroll
        for (int nt = 0; nt < 4; nt++) {
            int col = n0 + warpN * 32 + nt * 8 + t4 * 2;
            float b0 = bias[col], b1 = bias[col + 1];
            int r0 = m0 + warpM * 32 + mt * 16 + g;
            int r1 = r0 + 8;
            if (OUT_BF16) {
                if (r0 < M)
                    Cw[(size_t)r0 * ldcw + (col >> 1)] = pack_bf16x2(acc[mt][nt][0] + b0, acc[mt][nt][1] + b1);
                if (r1 < M)
                    Cw[(size_t)r1 * ldcw + (col >> 1)] = pack_bf16x2(acc[mt][nt][2] + b0, acc[mt][nt][3] + b1);
            } else {
                float* C = (float*)Cw;
                if (r0 < M) {
                    float2 v = make_float2(acc[mt][nt][0] + b0, acc[mt][nt][1] + b1);
                    *(float2*)&C[(size_t)r0 * ldcw + col] = v;
                }
                if (r1 < M) {
                    float2 v = make_float2(acc[mt][nt][2] + b0, acc[mt][nt][3] + b1);
                    *(float2*)&C[(size_t)r1 * ldcw + col] = v;
                }
            }
        }
    }
}

// ---------------------------------------------------------------------------
// Fused weight prep: computes the rel_att/rel_msg fold on the fly and writes
// the packed+permuted bf16 hi/lo weight images and fused biases directly.
// ---------------------------------------------------------------------------
__device__ __forceinline__ float wcat_val(int t, int i, int c,
                                          const float* Wk, const float* Wq, const float* Wv,
                                          const float* rel_att, const float* rel_msg) {
    if (c < 512) {
        int sel = c >> 7;
        int rel = (sel & 1) ? (t == 0 ? 2 : 3) : (t == 0 ? 0 : 1);
        int isV = sel >> 1;
        int o = c & 127, h = o >> 4, eo = o & 15;
        const float* Wsrc = (isV ? Wv : Wk) + (size_t)t * 16384 + (size_t)i * 128 + h * 16;
        const float* R = (isV ? rel_msg : rel_att) + (((size_t)rel * 8 + h) * 16) * 16 + eo;
        float a = 0.f;
#pragma unroll
        for (int d = 0; d < 16; d++) a += Wsrc[d] * R[d * 16];
        return a;
    }
    return Wq[(size_t)t * 16384 + (size_t)i * 128 + (c - 512)];
}

__global__ void setup_weights(const float* __restrict__ Wk, const float* __restrict__ bk,
                              const float* __restrict__ Wq, const float* __restrict__ bq,
                              const float* __restrict__ Wv, const float* __restrict__ bv,
                              const float* __restrict__ Wa,
                              const float* __restrict__ rel_att, const float* __restrict__ rel_msg) {
    uint32_t* W32 = (uint32_t*)g_buf;
    int idx = blockIdx.x * blockDim.x + threadIdx.x;
    int n_cat = 2 * 64 * NC;
    int n_wa  = 2 * 64 * 128;
    if (idx < n_cat) {
        int t  = idx / (64 * NC);
        int pk = (idx / NC) & 63;
        int n  = idx % NC;
        float w0 = wcat_val(t, 2 * pk,     n, Wk, Wq, Wv, rel_att, rel_msg);
        float w1 = wcat_val(t, 2 * pk + 1, n, Wk, Wq, Wv, rel_att, rel_msg);
        uint32_t h = pack_bf16x2(w0, w1);
        uint32_t l = pack_bf16x2(w0 - lo_as_f32(h), w1 - hi_as_f32(h));
        int p = wperm(n);
        W32[OFF_WH + (size_t)t * 64 * NC + (size_t)pk * NC + p] = h;
        W32[OFF_WL + (size_t)t * 64 * NC + (size_t)pk * NC + p] = l;
        if (pk == 0) {
            float bval;
            if (n < 512) {
                int sel = n >> 7;
                int rel = (sel & 1) ? (t == 0 ? 2 : 3) : (t == 0 ? 0 : 1);
                int isV = sel >> 1;
                int o = n & 127, hh = o >> 4, eo = o & 15;
                const float* bsrc = (isV ? bv : bk) + t * 128 + hh * 16;
                const float* R = (isV ? rel_msg : rel_att) + (((size_t)rel * 8 + hh) * 16) * 16 + eo;
                float b = 0.f;
#pragma unroll
                for (int d = 0; d < 16; d++) b += bsrc[d] * R[d * 16];
                bval = b;
            } else {
                bval = bq[t * 128 + (n - 512)];
            }
            g_buf[OFF_BCAT + t * NC + n] = bval;
        }
    } else if (idx < n_cat + n_wa) {
        int j  = idx - n_cat;
        int t  = j / (64 * 128);
        int pk = (j / 128) & 63;
        int n  = j % 128;
        float w0 = Wa[(size_t)t * 16384 + (size_t)(2 * pk)     * 128 + n];
        float w1 = Wa[(size_t)t * 16384 + (size_t)(2 * pk + 1) * 128 + n];
        uint32_t h = pack_bf16x2(w0, w1);
        uint32_t l = pack_bf16x2(w0 - lo_as_f32(h), w1 - hi_as_f32(h));
        int p = wperm(n);
        W32[OFF_WAH + (size_t)t * 64 * 128 + (size_t)pk * 128 + p] = h;
        W32[OFF_WAL + (size_t)t * 64 * 128 + (size_t)pk * 128 + p] = l;
    }
}

// ---------------------------------------------------------------------------
// Fused data setup: pack node features to bf16 hi/lo images AND zero the
// N16/DEN accumulator region. Two grid-stride loops, one launch.
// ---------------------------------------------------------------------------
__global__ void setup_data(const float* __restrict__ h0, const float* __restrict__ h1) {
    uint32_t* W32 = (uint32_t*)g_buf;
    size_t gid = (size_t)blockIdx.x * blockDim.x + threadIdx.x;
    size_t stride = (size_t)gridDim.x * blockDim.x;

    size_t totalx = (size_t)2 * NN * 64;
    for (size_t idx = gid; idx < totalx; idx += stride) {
        int t = (int)(idx / (NN * 64));
        size_t rem = idx - (size_t)t * (NN * 64);
        const float* h = t ? h1 : h0;
        float2 v = *(const float2*)&h[rem * 2];
        uint32_t hi = pack_bf16x2(v.x, v.y);
        uint32_t lo = pack_bf16x2(v.x - lo_as_f32(hi), v.y - hi_as_f32(hi));
        W32[OFF_XH + (size_t)t * NN * 64 + rem] = hi;
        W32[OFF_XL + (size_t)t * NN * 64 + rem] = lo;
    }

    uint4* p = (uint4*)(g_buf + OFF_N16);
    size_t n4 = ((size_t)4 * NN * 64 + (size_t)4 * NN * 8) / 4;
    uint4 z = make_uint4(0, 0, 0, 0);
    for (size_t i = gid; i < n4; i += stride) p[i] = z;
}

// ---------------------------------------------------------------------------
// Single edge pass over bf16 projections. One warp per edge.
// Numerator accumulated via f16x2 RED.
// ---------------------------------------------------------------------------
__global__ void edge_pass(const float* __restrict__ pri,
                          const int* __restrict__ s0, const int* __restrict__ d0,
                          const int* __restrict__ s1, const int* __restrict__ d1,
                          const int* __restrict__ s2, const int* __restrict__ d2,
                          const int* __restrict__ s3, const int* __restrict__ d3) {
    int r = blockIdx.y;
    int e = blockIdx.x * (blockDim.x >> 5) + (threadIdx.x >> 5);
    if (e >= EE) return;
    int lane = threadIdx.x & 31;

    const int* src = (r == 0) ? s0 : (r == 1) ? s1 : (r == 2) ? s2 : s3;
    const int* dst = (r == 0) ? d0 : (r == 1) ? d1 : (r == 2) ? d2 : d3;
    int st = r & 1;
    int dt = (r == 0 || r == 3) ? 1 : 0;
    int sliceKVw = (r >> 1) * 64;

    int s = src[e];
    int d = dst[e];

    const uint32_t* Cw = (const uint32_t*)g_buf;
    const uint32_t* Cs = Cw + (st ? OFF_C1 : OFF_C0) + (size_t)s * NCW;
    const uint32_t* Cd = Cw + (dt ? OFF_C1 : OFF_C0) + (size_t)d * NCW;

    uint2 qw = *(const uint2*)&Cd[256 + lane * 2];
    uint2 kw = *(const uint2*)&Cs[sliceKVw + lane * 2];
    float p = lo_as_f32(qw.x) * lo_as_f32(kw.x) + hi_as_f32(qw.x) * hi_as_f32(kw.x)
            + lo_as_f32(qw.y) * lo_as_f32(kw.y) + hi_as_f32(qw.y) * hi_as_f32(kw.y);
    p += __shfl_xor_sync(0xffffffffu, p, 1);
    p += __shfl_xor_sync(0xffffffffu, p, 2);
    int h = lane >> 2;
    float sc = p * pri[r * 8 + h] * 0.25f;
    float ex = __expf(sc);

    if ((lane & 3) == 0) {
        float* dp = g_buf + OFF_DEN + ((size_t)r * NN + d) * 8 + h;
        asm volatile("red.global.add.f32 [%0], %1;" :: "l"(dp), "f"(ex) : "memory");
    }

    uint2 vw = *(const uint2*)&Cs[128 + sliceKVw + lane * 2];
    float p0 = lo_as_f32(vw.x) * ex, p1 = hi_as_f32(vw.x) * ex;
    float p2 = lo_as_f32(vw.y) * ex, p3 = hi_as_f32(vw.y) * ex;
    uint32_t w0 = pack_f16x2(p0, p1);
    uint32_t w1 = pack_f16x2(p2, p3);
    uint32_t* np = (uint32_t*)g_buf + OFF_N16 + ((size_t)r * NN + d) * 64 + lane * 2;
    asm volatile("red.global.add.noftz.f16x2 [%0], %1;" :: "l"(np),     "r"(w0) : "memory");
    asm volatile("red.global.add.noftz.f16x2 [%0], %1;" :: "l"(np + 1), "r"(w1) : "memory");
}

// ---------------------------------------------------------------------------
// Normalize + cross-relation mean; reads f16x2 numerator; emits packed bf16
// hi/lo AGG images
// ---------------------------------------------------------------------------
__global__ void agg_pack() {
    uint32_t* W32 = (uint32_t*)g_buf;
    const uint32_t* N16 = (const uint32_t*)g_buf + OFF_N16;
    size_t total = (size_t)2 * NN * 64;
    size_t i = (size_t)blockIdx.x * blockDim.x + threadIdx.x;
    size_t stride = (size_t)gridDim.x * blockDim.x;
    for (; i < total; i += stride) {
        int w = (int)(i & 63);
        size_t nt = i >> 6;
        int t = (int)(nt / NN);
        int n = (int)(nt % NN);
        int rA = (t == 0) ? 1 : 0;
        int rB = (t == 0) ? 2 : 3;
        int h = w >> 3;
        float dA = g_buf[OFF_DEN + ((size_t)rA * NN + n) * 8 + h];
        float dB = g_buf[OFF_DEN + ((size_t)rB * NN + n) * 8 + h];
        float iA = (dA > 0.f) ? 0.5f / dA : 0.f;
        float iB = (dB > 0.f) ? 0.5f / dB : 0.f;
        uint32_t wA = N16[((size_t)rA * NN + n) * 64 + w];
        uint32_t wB = N16[((size_t)rB * NN + n) * 64 + w];
        float2 fA = __half22float2(*(const __half2*)&wA);
        float2 fB = __half22float2(*(const __half2*)&wB);
        float a0 = fA.x * iA + fB.x * iB;
        float a1 = fA.y * iA + fB.y * iB;
        uint32_t hi = pack_bf16x2(a0, a1);
        uint32_t lo = pack_bf16x2(a0 - lo_as_f32(hi), a1 - hi_as_f32(hi));
        W32[OFF_AGGH + i] = hi;
        W32[OFF_AGGL + i] = lo;
    }
}

// ---------------------------------------------------------------------------
// Skip + LayerNorm. One warp per row.
// ---------------------------------------------------------------------------
__global__ void ln_kernel(const float* __restrict__ h0, const float* __restrict__ h1,
                          const float* __restrict__ skip,
                          const float* __restrict__ ln_g, const float* __restrict__ ln_b,
                          float* __restrict__ out) {
    int warp = (blockIdx.x * blockDim.x + threadIdx.x) >> 5;
    int lane = threadIdx.x & 31;
    if (warp >= 2 * NN) return;
    int t = warp / NN;
    int n = warp % NN;

    const float* hh = (t == 0) ? h0 : h1;
    const float* tr = g_buf + OFF_TRANS + ((size_t)t * NN + n) * 128;
    float alpha = 1.f / (1.f + __expf(-skip[t]));
    float beta = 1.f - alpha;

    float4 tv = *(const float4*)&tr[lane * 4];
    float4 hv = *(const float4*)&hh[(size_t)n * 128 + lane * 4];
    float4 x;
    x.x = tv.x * alpha + hv.x * beta;
    x.y = tv.y * alpha + hv.y * beta;
    x.z = tv.z * alpha + hv.z * beta;
    x.w = tv.w * alpha + hv.w * beta;

    float s1 = x.x + x.y + x.z + x.w;
    float s2 = x.x * x.x + x.y * x.y + x.z * x.z + x.w * x.w;
#pragma unroll
    for (int o = 16; o >= 1; o >>= 1) {
        s1 += __shfl_xor_sync(0xffffffffu, s1, o);
        s2 += __shfl_xor_sync(0xffffffffu, s2, o);
    }
    float mean = s1 * (1.f / 128.f);
    float var  = s2 * (1.f / 128.f) - mean * mean;
    float rstd = rsqrtf(var + 1e-5f);

    int j = lane * 4;
    float4 g4 = *(const float4*)&ln_g[t * 128 + j];
    float4 b4 = *(const float4*)&ln_b[t * 128 + j];
    float4 o4;
    o4.x = (x.x - mean) * rstd * g4.x + b4.x;
    o4.y = (x.y - mean) * rstd * g4.y + b4.y;
    o4.z = (x.z - mean) * rstd * g4.z + b4.z;
    o4.w = (x.w - mean) * rstd * g4.w + b4.w;
    *(float4*)&out[((size_t)t * NN + n) * 128 + j] = o4;
}

// ---------------------------------------------------------------------------
// Host launcher
// ---------------------------------------------------------------------------
extern "C" void kernel_launch(void* const* d_in, const int* in_sizes, int n_in,
                              void* d_out, int out_size) {
    const float* h0 = (const float*)d_in[0];
    const float* h1 = (const float*)d_in[1];
    const int* s0 = (const int*)d_in[2];
    const int* d0 = (const int*)d_in[3];
    const int* s1 = (const int*)d_in[4];
    const int* d1 = (const int*)d_in[5];
    const int* s2 = (const int*)d_in[6];
    const int* d2 = (const int*)d_in[7];
    const int* s3 = (const int*)d_in[8];
    const int* d3 = (const int*)d_in[9];
    const float* Wk = (const float*)d_in[10];
    const float* bk = (const float*)d_in[11];
    const float* Wq = (const float*)d_in[12];
    const float* bq = (const float*)d_in[13];
    const float* Wv = (const float*)d_in[14];
    const float* bv = (const float*)d_in[15];
    const float* Wa = (const float*)d_in[16];
    const float* ba = (const float*)d_in[17];
    const float* rel_att = (const float*)d_in[18];
    const float* rel_msg = (const float*)d_in[19];
    const float* rel_pri = (const float*)d_in[20];
    const float* skip = (const float*)d_in[21];
    const float* ln_g = (const float*)d_in[22];
    const float* ln_b = (const float*)d_in[23];

    static float* buf = nullptr;
    if (!buf) {
        cudaGetSymbolAddress((void**)&buf, g_buf);
        cudaFuncSetAttribute(gemm3<true>,  cudaFuncAttributeMaxDynamicSharedMemorySize, GSMEM_BYTES);
        cudaFuncSetAttribute(gemm3<false>, cudaFuncAttributeMaxDynamicSharedMemorySize, GSMEM_BYTES);
    }
    uint32_t* buf32 = (uint32_t*)buf;

    // 1) fused setup: weights (fold+pack) and data (feature pack + accum zero)
    setup_weights<<<(2 * 64 * NC + 2 * 64 * 128 + 255) / 256, 256>>>(
        Wk, bk, Wq, bq, Wv, bv, Wa, rel_att, rel_msg);
    setup_data<<<2048, 256>>>(h0, h1);

    // 2) fused KVQ projections: per type, [NN,128] x [128,640] -> bf16 packed
    int mblocks = (NN + BM - 1) / BM;
    for (int t = 0; t < 2; t++) {
        dim3 gg(mblocks, NC / BN);
        gemm3<true><<<gg, 256, GSMEM_BYTES>>>(
            buf32 + OFF_XH + (size_t)t * NN * 64,
            buf32 + OFF_XL + (size_t)t * NN * 64,
            buf32 + OFF_WH + (size_t)t * 64 * NC,
            buf32 + OFF_WL + (size_t)t * 64 * NC, NC,
            buf + OFF_BCAT + t * NC,
            buf32 + (t ? OFF_C1 : OFF_C0), NCW, NN);
    }

    // 3) single edge pass (all 4 relations; f16x2 numerator RED)
    dim3 gE((EE + 7) / 8, 4);
    edge_pass<<<gE, 256>>>(rel_pri, s0, d0, s1, d1, s2, d2, s3, d3);

    // 4) normalize + mean -> packed AGG images
    agg_pack<<<2048, 256>>>();

    // 5) output projection [NN,128] x [128,128] per type (fp32 out)
    for (int t = 0; t < 2; t++) {
        dim3 gg(mblocks, 128 / BN);
        gemm3<false><<<gg, 256, GSMEM_BYTES>>>(
            buf32 + OFF_AGGH + (size_t)t * NN * 64,
            buf32 + OFF_AGGL + (size_t)t * NN * 64,
            buf32 + OFF_WAH + (size_t)t * 64 * 128,
            buf32 + OFF_WAL + (size_t)t * 64 * 128, 128,
            ba + t * 128,
            (uint32_t*)(buf + OFF_TRANS + (size_t)t * NN * 128), 128, NN);
    }

    // 6) skip + layernorm -> out
    ln_kernel<<<(2 * NN * 32 + 255) / 256, 256>>>(h0, h1, skip, ln_g, ln_b, (float*)d_out);
}

// round 16
// speedup vs baseline: 1.0479x; 1.0198x over previous
#include <cuda_runtime.h>
#include <cuda_bf16.h>
#include <cuda_fp16.h>
#include <cstdint>
#include <math.h>

// ---------------------------------------------------------------------------
// Problem constants
// ---------------------------------------------------------------------------
#define NN 50000      // nodes per type
#define EE 200000     // edges per relation
// REL = [(0,1),(1,0),(0,0),(1,1)]
#define NC 640        // fused projection width: [K_rA | K_rB | V_rA | V_rB | Q]
#define NCW 320       // bf16-packed row width in 32-bit words

// ---------------------------------------------------------------------------
// Scratch layout (32-bit words)
// ---------------------------------------------------------------------------
constexpr size_t OFF_C0    = 0;                                  // NN*320 (bf16x2)
constexpr size_t OFF_C1    = OFF_C0    + (size_t)NN * NCW;
constexpr size_t OFF_N16   = OFF_C1    + (size_t)NN * NCW;       // 4*NN*64 (f16x2 words)
constexpr size_t OFF_DEN   = OFF_N16   + (size_t)4 * NN * 64;    // 4*NN*8 fp32
constexpr size_t OFF_TRANS = OFF_DEN   + (size_t)4 * NN * 8;     // 2*NN*128 fp32
constexpr size_t OFF_AGGH  = OFF_TRANS + (size_t)2 * NN * 128;   // 2*NN*64 bf16x2
constexpr size_t OFF_AGGL  = OFF_AGGH  + (size_t)2 * NN * 64;
constexpr size_t OFF_XH    = OFF_AGGL  + (size_t)2 * NN * 64;    // 2*NN*64
constexpr size_t OFF_XL    = OFF_XH    + (size_t)2 * NN * 64;
constexpr size_t OFF_BCAT  = OFF_XL    + (size_t)2 * NN * 64;    // 2*640 fp32
constexpr size_t OFF_WH    = OFF_BCAT  + (size_t)2 * NC;         // 2*64*640
constexpr size_t OFF_WL    = OFF_WH    + (size_t)2 * 64 * NC;
constexpr size_t OFF_WAH   = OFF_WL    + (size_t)2 * 64 * NC;    // 2*64*128
constexpr size_t OFF_WAL   = OFF_WAH   + (size_t)2 * 64 * 128;
constexpr size_t BUF_TOTAL = OFF_WAL   + (size_t)2 * 64 * 128;

__device__ float g_buf[BUF_TOTAL];

// ---------------------------------------------------------------------------
// helpers
// ---------------------------------------------------------------------------
__device__ __forceinline__ uint32_t pack_bf16x2(float x, float y) {
    uint32_t r;
    asm("cvt.rn.bf16x2.f32 %0, %1, %2;" : "=r"(r) : "f"(y), "f"(x));
    return r;
}
__device__ __forceinline__ uint32_t pack_f16x2(float x, float y) {
    uint32_t r;
    asm("cvt.rn.f16x2.f32 %0, %1, %2;" : "=r"(r) : "f"(y), "f"(x));
    return r;
}
__device__ __forceinline__ float lo_as_f32(uint32_t p) { return __uint_as_float(p << 16); }
__device__ __forceinline__ float hi_as_f32(uint32_t p) { return __uint_as_float(p & 0xffff0000u); }

__device__ __forceinline__ void mma_bf16(float* c, const uint32_t* a, const uint32_t* b) {
    asm volatile(
        "mma.sync.aligned.m16n8k16.row.col.f32.bf16.bf16.f32 "
        "{%0,%1,%2,%3}, {%4,%5,%6,%7}, {%8,%9}, {%0,%1,%2,%3};"
        : "+f"(c[0]), "+f"(c[1]), "+f"(c[2]), "+f"(c[3])
        : "r"(a[0]), "r"(a[1]), "r"(a[2]), "r"(a[3]), "r"(b[0]), "r"(b[1]));
}

__device__ __forceinline__ void ldsm_x4(uint32_t* r, uint32_t addr) {
    asm volatile("ldmatrix.sync.aligned.m8n8.x4.shared.b16 {%0,%1,%2,%3}, [%4];"
                 : "=r"(r[0]), "=r"(r[1]), "=r"(r[2]), "=r"(r[3]) : "r"(addr));
}

__device__ __forceinline__ void cp_async16(uint32_t dst, const void* src, int srcbytes) {
    asm volatile("cp.async.cg.shared.global [%0], [%1], 16, %2;"
                 :: "r"(dst), "l"(src), "r"(srcbytes) : "memory");
}

__host__ __device__ __forceinline__ int wperm(int n) {
    return (n & ~63) | (((n & 7) << 3) | ((n >> 3) & 7));
}

// ---------------------------------------------------------------------------
// 3xBF16 tensor-core GEMM. launch_bounds(256,3): cap regs so 3 CTAs/SM fit
// (register file was the occupancy limiter at 86 regs -> 2 CTAs).
// ---------------------------------------------------------------------------
#define BM 128
#define BN 64
#define APITCH 20
#define A_STG (BM * APITCH)
#define W_STG (16 * 72)
#define GSMEM_WORDS (4 * A_STG + 4 * W_STG)
#define GSMEM_BYTES (GSMEM_WORDS * 4)

template<bool OUT_BF16>
__global__ __launch_bounds__(256, 3) void gemm3(const uint32_t* __restrict__ AH,
                                                const uint32_t* __restrict__ AL,
                                                const uint32_t* __restrict__ WH,
                                                const uint32_t* __restrict__ WL,
                                                int ldww,
                                                const float* __restrict__ bias,
                                                uint32_t* __restrict__ Cw, int ldcw,
                                                int M) {
    extern __shared__ uint32_t sm[];
    uint32_t smbase = (uint32_t)__cvta_generic_to_shared(sm);

    int tid  = threadIdx.x;
    int warp = tid >> 5;
    int lane = tid & 31;
    int g    = lane >> 2;
    int t4   = lane & 3;
    int warpM = warp >> 1;
    int warpN = warp & 1;

    int m0 = blockIdx.x * BM;
    int n0 = blockIdx.y * BN;

    int lrow  = lane & 15;
    int lcolw = (lane >> 4) * 4;

    float acc[2][4][4];
#pragma unroll
    for (int i = 0; i < 2; i++)
#pragma unroll
        for (int j = 0; j < 4; j++)
#pragma unroll
            for (int k = 0; k < 4; k++) acc[i][j][k] = 0.f;

    auto stage_load = [&](int s, int kb) {
        int kb2 = kb >> 1;
#pragma unroll
        for (int i = 0; i < 2; i++) {
            int c   = i * 256 + tid;
            int row = c >> 2;
            int cw  = (c & 3) * 4;
            int m   = m0 + row;
            int ok  = (m < M) ? 16 : 0;
            size_t srcoff = (size_t)(m < M ? m : M - 1) * 64 + kb2 + cw;
            uint32_t dH = smbase + (uint32_t)((s * A_STG + row * APITCH + cw) * 4);
            uint32_t dL = smbase + (uint32_t)(((2 + s) * A_STG + row * APITCH + cw) * 4);
            cp_async16(dH, AH + srcoff, ok);
            cp_async16(dL, AL + srcoff, ok);
        }
        {
            int pk = tid >> 4;
            int cg = tid & 15;
            size_t srcoff = (size_t)(kb2 + pk) * ldww + n0 + cg * 4;
            uint32_t dH = smbase + (uint32_t)((4 * A_STG + s * W_STG + pk * 72 + cg * 4) * 4);
            uint32_t dL = smbase + (uint32_t)((4 * A_STG + (2 + s) * W_STG + pk * 72 + cg * 4) * 4);
            cp_async16(dH, WH + srcoff, 16);
            cp_async16(dL, WL + srcoff, 16);
        }
        asm volatile("cp.async.commit_group;" ::: "memory");
    };

    stage_load(0, 0);

    int s = 0;
    for (int kb = 0; kb < 128; kb += 32, s ^= 1) {
        if (kb + 32 < 128) {
            stage_load(s ^ 1, kb + 32);
            asm volatile("cp.async.wait_group 1;" ::: "memory");
        } else {
            asm volatile("cp.async.wait_group 0;" ::: "memory");
        }
        __syncthreads();

        uint32_t asHs = smbase + (uint32_t)(s * A_STG * 4);
        uint32_t asLs = smbase + (uint32_t)((2 + s) * A_STG * 4);
        const uint32_t* wsH = sm + 4 * A_STG + s * W_STG;
        const uint32_t* wsL = sm + 4 * A_STG + (2 + s) * W_STG;

#pragma unroll
        for (int ks = 0; ks < 2; ks++) {
            int kp = ks * 8;
            uint32_t ah[2][4], al[2][4];
#pragma unroll
            for (int mt = 0; mt < 2; mt++) {
                int rb = warpM * 32 + mt * 16;
                uint32_t off = (uint32_t)(((rb + lrow) * APITCH + kp + lcolw) * 4);
                ldsm_x4(ah[mt], asHs + off);
                ldsm_x4(al[mt], asLs + off);
            }
            int colw = g * 8 + warpN * 4;
            uint4 bh0 = *(const uint4*)&wsH[(kp + t4) * 72 + colw];
            uint4 bh1 = *(const uint4*)&wsH[(kp + t4 + 4) * 72 + colw];
            uint4 bl0 = *(const uint4*)&wsL[(kp + t4) * 72 + colw];
            uint4 bl1 = *(const uint4*)&wsL[(kp + t4 + 4) * 72 + colw];
            const uint32_t* ph0 = (const uint32_t*)&bh0;
            const uint32_t* ph1 = (const uint32_t*)&bh1;
            const uint32_t* pl0 = (const uint32_t*)&bl0;
            const uint32_t* pl1 = (const uint32_t*)&bl1;
#pragma unroll
            for (int nt = 0; nt < 4; nt++) {
                uint32_t bh[2] = {ph0[nt], ph1[nt]};
                uint32_t bl[2] = {pl0[nt], pl1[nt]};
#pragma unroll
                for (int mt = 0; mt < 2; mt++) {
                    mma_bf16(acc[mt][nt], ah[mt], bh);
                    mma_bf16(acc[mt][nt], ah[mt], bl);
                    mma_bf16(acc[mt][nt], al[mt], bh);
                }
            }
        }
        __syncthreads();
    }

#pragma unroll
    for (int mt = 0; mt < 2; mt++) {
#pragma unroll
        for (int nt = 0; nt < 4; nt++) {
            int col = n0 + warpN * 32 + nt * 8 + t4 * 2;
            float b0 = bias[col], b1 = bias[col + 1];
            int r0 = m0 + warpM * 32 + mt * 16 + g;
            int r1 = r0 + 8;
            if (OUT_BF16) {
                if (r0 < M)
                    Cw[(size_t)r0 * ldcw + (col >> 1)] = pack_bf16x2(acc[mt][nt][0] + b0, acc[mt][nt][1] + b1);
                if (r1 < M)
                    Cw[(size_t)r1 * ldcw + (col >> 1)] = pack_bf16x2(acc[mt][nt][2] + b0, acc[mt][nt][3] + b1);
            } else {
                float* C = (float*)Cw;
                if (r0 < M) {
                    float2 v = make_float2(acc[mt][nt][0] + b0, acc[mt][nt][1] + b1);
                    *(float2*)&C[(size_t)r0 * ldcw + col] = v;
                }
                if (r1 < M) {
                    float2 v = make_float2(acc[mt][nt][2] + b0, acc[mt][nt][3] + b1);
                    *(float2*)&C[(size_t)r1 * ldcw + col] = v;
                }
            }
        }
    }
}

// ---------------------------------------------------------------------------
// Fused weight prep: computes the rel_att/rel_msg fold on the fly and writes
// the packed+permuted bf16 hi/lo weight images and fused biases directly.
// ---------------------------------------------------------------------------
__device__ __forceinline__ float wcat_val(int t, int i, int c,
                                          const float* Wk, const float* Wq, const float* Wv,
                                          const float* rel_att, const float* rel_msg) {
    if (c < 512) {
        int sel = c >> 7;
        int rel = (sel & 1) ? (t == 0 ? 2 : 3) : (t == 0 ? 0 : 1);
        int isV = sel >> 1;
        int o = c & 127, h = o >> 4, eo = o & 15;
        const float* Wsrc = (isV ? Wv : Wk) + (size_t)t * 16384 + (size_t)i * 128 + h * 16;
        const float* R = (isV ? rel_msg : rel_att) + (((size_t)rel * 8 + h) * 16) * 16 + eo;
        float a = 0.f;
#pragma unroll
        for (int d = 0; d < 16; d++) a += Wsrc[d] * R[d * 16];
        return a;
    }
    return Wq[(size_t)t * 16384 + (size_t)i * 128 + (c - 512)];
}

__global__ void setup_weights(const float* __restrict__ Wk, const float* __restrict__ bk,
                              const float* __restrict__ Wq, const float* __restrict__ bq,
                              const float* __restrict__ Wv, const float* __restrict__ bv,
                              const float* __restrict__ Wa,
                              const float* __restrict__ rel_att, const float* __restrict__ rel_msg) {
    uint32_t* W32 = (uint32_t*)g_buf;
    int idx = blockIdx.x * blockDim.x + threadIdx.x;
    int n_cat = 2 * 64 * NC;
    int n_wa  = 2 * 64 * 128;
    if (idx < n_cat) {
        int t  = idx / (64 * NC);
        int pk = (idx / NC) & 63;
        int n  = idx % NC;
        float w0 = wcat_val(t, 2 * pk,     n, Wk, Wq, Wv, rel_att, rel_msg);
        float w1 = wcat_val(t, 2 * pk + 1, n, Wk, Wq, Wv, rel_att, rel_msg);
        uint32_t h = pack_bf16x2(w0, w1);
        uint32_t l = pack_bf16x2(w0 - lo_as_f32(h), w1 - hi_as_f32(h));
        int p = wperm(n);
        W32[OFF_WH + (size_t)t * 64 * NC + (size_t)pk * NC + p] = h;
        W32[OFF_WL + (size_t)t * 64 * NC + (size_t)pk * NC + p] = l;
        if (pk == 0) {
            float bval;
            if (n < 512) {
                int sel = n >> 7;
                int rel = (sel & 1) ? (t == 0 ? 2 : 3) : (t == 0 ? 0 : 1);
                int isV = sel >> 1;
                int o = n & 127, hh = o >> 4, eo = o & 15;
                const float* bsrc = (isV ? bv : bk) + t * 128 + hh * 16;
                const float* R = (isV ? rel_msg : rel_att) + (((size_t)rel * 8 + hh) * 16) * 16 + eo;
                float b = 0.f;
#pragma unroll
                for (int d = 0; d < 16; d++) b += bsrc[d] * R[d * 16];
                bval = b;
            } else {
                bval = bq[t * 128 + (n - 512)];
            }
            g_buf[OFF_BCAT + t * NC + n] = bval;
        }
    } else if (idx < n_cat + n_wa) {
        int j  = idx - n_cat;
        int t  = j / (64 * 128);
        int pk = (j / 128) & 63;
        int n  = j % 128;
        float w0 = Wa[(size_t)t * 16384 + (size_t)(2 * pk)     * 128 + n];
        float w1 = Wa[(size_t)t * 16384 + (size_t)(2 * pk + 1) * 128 + n];
        uint32_t h = pack_bf16x2(w0, w1);
        uint32_t l = pack_bf16x2(w0 - lo_as_f32(h), w1 - hi_as_f32(h));
        int p = wperm(n);
        W32[OFF_WAH + (size_t)t * 64 * 128 + (size_t)pk * 128 + p] = h;
        W32[OFF_WAL + (size_t)t * 64 * 128 + (size_t)pk * 128 + p] = l;
    }
}

// ---------------------------------------------------------------------------
// Fused data setup: pack node features to bf16 hi/lo images AND zero the
// N16/DEN accumulator region.
// ---------------------------------------------------------------------------
__global__ void setup_data(const float* __restrict__ h0, const float* __restrict__ h1) {
    uint32_t* W32 = (uint32_t*)g_buf;
    size_t gid = (size_t)blockIdx.x * blockDim.x + threadIdx.x;
    size_t stride = (size_t)gridDim.x * blockDim.x;

    size_t totalx = (size_t)2 * NN * 64;
    for (size_t idx = gid; idx < totalx; idx += stride) {
        int t = (int)(idx / (NN * 64));
        size_t rem = idx - (size_t)t * (NN * 64);
        const float* h = t ? h1 : h0;
        float2 v = *(const float2*)&h[rem * 2];
        uint32_t hi = pack_bf16x2(v.x, v.y);
        uint32_t lo = pack_bf16x2(v.x - lo_as_f32(hi), v.y - hi_as_f32(hi));
        W32[OFF_XH + (size_t)t * NN * 64 + rem] = hi;
        W32[OFF_XL + (size_t)t * NN * 64 + rem] = lo;
    }

    uint4* p = (uint4*)(g_buf + OFF_N16);
    size_t n4 = ((size_t)4 * NN * 64 + (size_t)4 * NN * 8) / 4;
    uint4 z = make_uint4(0, 0, 0, 0);
    for (size_t i = gid; i < n4; i += stride) p[i] = z;
}

// ---------------------------------------------------------------------------
// Single edge pass over bf16 projections. One warp per edge.
// Numerator accumulated via f16x2 RED.
// ---------------------------------------------------------------------------
__global__ void edge_pass(const float* __restrict__ pri,
                          const int* __restrict__ s0, const int* __restrict__ d0,
                          const int* __restrict__ s1, const int* __restrict__ d1,
                          const int* __restrict__ s2, const int* __restrict__ d2,
                          const int* __restrict__ s3, const int* __restrict__ d3) {
    int r = blockIdx.y;
    int e = blockIdx.x * (blockDim.x >> 5) + (threadIdx.x >> 5);
    if (e >= EE) return;
    int lane = threadIdx.x & 31;

    const int* src = (r == 0) ? s0 : (r == 1) ? s1 : (r == 2) ? s2 : s3;
    const int* dst = (r == 0) ? d0 : (r == 1) ? d1 : (r == 2) ? d2 : d3;
    int st = r & 1;
    int dt = (r == 0 || r == 3) ? 1 : 0;
    int sliceKVw = (r >> 1) * 64;

    int s = src[e];
    int d = dst[e];

    const uint32_t* Cw = (const uint32_t*)g_buf;
    const uint32_t* Cs = Cw + (st ? OFF_C1 : OFF_C0) + (size_t)s * NCW;
    const uint32_t* Cd = Cw + (dt ? OFF_C1 : OFF_C0) + (size_t)d * NCW;

    uint2 qw = *(const uint2*)&Cd[256 + lane * 2];
    uint2 kw = *(const uint2*)&Cs[sliceKVw + lane * 2];
    float p = lo_as_f32(qw.x) * lo_as_f32(kw.x) + hi_as_f32(qw.x) * hi_as_f32(kw.x)
            + lo_as_f32(qw.y) * lo_as_f32(kw.y) + hi_as_f32(qw.y) * hi_as_f32(kw.y);
    p += __shfl_xor_sync(0xffffffffu, p, 1);
    p += __shfl_xor_sync(0xffffffffu, p, 2);
    int h = lane >> 2;
    float sc = p * pri[r * 8 + h] * 0.25f;
    float ex = __expf(sc);

    if ((lane & 3) == 0) {
        float* dp = g_buf + OFF_DEN + ((size_t)r * NN + d) * 8 + h;
        asm volatile("red.global.add.f32 [%0], %1;" :: "l"(dp), "f"(ex) : "memory");
    }

    uint2 vw = *(const uint2*)&Cs[128 + sliceKVw + lane * 2];
    float p0 = lo_as_f32(vw.x) * ex, p1 = hi_as_f32(vw.x) * ex;
    float p2 = lo_as_f32(vw.y) * ex, p3 = hi_as_f32(vw.y) * ex;
    uint32_t w0 = pack_f16x2(p0, p1);
    uint32_t w1 = pack_f16x2(p2, p3);
    uint32_t* np = (uint32_t*)g_buf + OFF_N16 + ((size_t)r * NN + d) * 64 + lane * 2;
    asm volatile("red.global.add.noftz.f16x2 [%0], %1;" :: "l"(np),     "r"(w0) : "memory");
    asm volatile("red.global.add.noftz.f16x2 [%0], %1;" :: "l"(np + 1), "r"(w1) : "memory");
}

// ---------------------------------------------------------------------------
// Normalize + cross-relation mean; reads f16x2 numerator; emits packed bf16
// hi/lo AGG images
// ---------------------------------------------------------------------------
__global__ void agg_pack() {
    uint32_t* W32 = (uint32_t*)g_buf;
    const uint32_t* N16 = (const uint32_t*)g_buf + OFF_N16;
    size_t total = (size_t)2 * NN * 64;
    size_t i = (size_t)blockIdx.x * blockDim.x + threadIdx.x;
    size_t stride = (size_t)gridDim.x * blockDim.x;
    for (; i < total; i += stride) {
        int w = (int)(i & 63);
        size_t nt = i >> 6;
        int t = (int)(nt / NN);
        int n = (int)(nt % NN);
        int rA = (t == 0) ? 1 : 0;
        int rB = (t == 0) ? 2 : 3;
        int h = w >> 3;
        float dA = g_buf[OFF_DEN + ((size_t)rA * NN + n) * 8 + h];
        float dB = g_buf[OFF_DEN + ((size_t)rB * NN + n) * 8 + h];
        float iA = (dA > 0.f) ? 0.5f / dA : 0.f;
        float iB = (dB > 0.f) ? 0.5f / dB : 0.f;
        uint32_t wA = N16[((size_t)rA * NN + n) * 64 + w];
        uint32_t wB = N16[((size_t)rB * NN + n) * 64 + w];
        float2 fA = __half22float2(*(const __half2*)&wA);
        float2 fB = __half22float2(*(const __half2*)&wB);
        float a0 = fA.x * iA + fB.x * iB;
        float a1 = fA.y * iA + fB.y * iB;
        uint32_t hi = pack_bf16x2(a0, a1);
        uint32_t lo = pack_bf16x2(a0 - lo_as_f32(hi), a1 - hi_as_f32(hi));
        W32[OFF_AGGH + i] = hi;
        W32[OFF_AGGL + i] = lo;
    }
}

// ---------------------------------------------------------------------------
// Skip + LayerNorm. One warp per row.
// ---------------------------------------------------------------------------
__global__ void ln_kernel(const float* __restrict__ h0, const float* __restrict__ h1,
                          const float* __restrict__ skip,
                          const float* __restrict__ ln_g, const float* __restrict__ ln_b,
                          float* __restrict__ out) {
    int warp = (blockIdx.x * blockDim.x + threadIdx.x) >> 5;
    int lane = threadIdx.x & 31;
    if (warp >= 2 * NN) return;
    int t = warp / NN;
    int n = warp % NN;

    const float* hh = (t == 0) ? h0 : h1;
    const float* tr = g_buf + OFF_TRANS + ((size_t)t * NN + n) * 128;
    float alpha = 1.f / (1.f + __expf(-skip[t]));
    float beta = 1.f - alpha;

    float4 tv = *(const float4*)&tr[lane * 4];
    float4 hv = *(const float4*)&hh[(size_t)n * 128 + lane * 4];
    float4 x;
    x.x = tv.x * alpha + hv.x * beta;
    x.y = tv.y * alpha + hv.y * beta;
    x.z = tv.z * alpha + hv.z * beta;
    x.w = tv.w * alpha + hv.w * beta;

    float s1 = x.x + x.y + x.z + x.w;
    float s2 = x.x * x.x + x.y * x.y + x.z * x.z + x.w * x.w;
#pragma unroll
    for (int o = 16; o >= 1; o >>= 1) {
        s1 += __shfl_xor_sync(0xffffffffu, s1, o);
        s2 += __shfl_xor_sync(0xffffffffu, s2, o);
    }
    float mean = s1 * (1.f / 128.f);
    float var  = s2 * (1.f / 128.f) - mean * mean;
    float rstd = rsqrtf(var + 1e-5f);

    int j = lane * 4;
    float4 g4 = *(const float4*)&ln_g[t * 128 + j];
    float4 b4 = *(const float4*)&ln_b[t * 128 + j];
    float4 o4;
    o4.x = (x.x - mean) * rstd * g4.x + b4.x;
    o4.y = (x.y - mean) * rstd * g4.y + b4.y;
    o4.z = (x.z - mean) * rstd * g4.z + b4.z;
    o4.w = (x.w - mean) * rstd * g4.w + b4.w;
    *(float4*)&out[((size_t)t * NN + n) * 128 + j] = o4;
}

// ---------------------------------------------------------------------------
// Host launcher
// ---------------------------------------------------------------------------
extern "C" void kernel_launch(void* const* d_in, const int* in_sizes, int n_in,
                              void* d_out, int out_size) {
    const float* h0 = (const float*)d_in[0];
    const float* h1 = (const float*)d_in[1];
    const int* s0 = (const int*)d_in[2];
    const int* d0 = (const int*)d_in[3];
    const int* s1 = (const int*)d_in[4];
    const int* d1 = (const int*)d_in[5];
    const int* s2 = (const int*)d_in[6];
    const int* d2 = (const int*)d_in[7];
    const int* s3 = (const int*)d_in[8];
    const int* d3 = (const int*)d_in[9];
    const float* Wk = (const float*)d_in[10];
    const float* bk = (const float*)d_in[11];
    const float* Wq = (const float*)d_in[12];
    const float* bq = (const float*)d_in[13];
    const float* Wv = (const float*)d_in[14];
    const float* bv = (const float*)d_in[15];
    const float* Wa = (const float*)d_in[16];
    const float* ba = (const float*)d_in[17];
    const float* rel_att = (const float*)d_in[18];
    const float* rel_msg = (const float*)d_in[19];
    const float* rel_pri = (const float*)d_in[20];
    const float* skip = (const float*)d_in[21];
    const float* ln_g = (const float*)d_in[22];
    const float* ln_b = (const float*)d_in[23];

    static float* buf = nullptr;
    if (!buf) {
        cudaGetSymbolAddress((void**)&buf, g_buf);
        cudaFuncSetAttribute(gemm3<true>,  cudaFuncAttributeMaxDynamicSharedMemorySize, GSMEM_BYTES);
        cudaFuncSetAttribute(gemm3<false>, cudaFuncAttributeMaxDynamicSharedMemorySize, GSMEM_BYTES);
    }
    uint32_t* buf32 = (uint32_t*)buf;

    // 1) fused setup: weights (fold+pack) and data (feature pack + accum zero)
    setup_weights<<<(2 * 64 * NC + 2 * 64 * 128 + 255) / 256, 256>>>(
        Wk, bk, Wq, bq, Wv, bv, Wa, rel_att, rel_msg);
    setup_data<<<2048, 256>>>(h0, h1);

    // 2) fused KVQ projections: per type, [NN,128] x [128,640] -> bf16 packed
    int mblocks = (NN + BM - 1) / BM;
    for (int t = 0; t < 2; t++) {
        dim3 gg(mblocks, NC / BN);
        gemm3<true><<<gg, 256, GSMEM_BYTES>>>(
            buf32 + OFF_XH + (size_t)t * NN * 64,
            buf32 + OFF_XL + (size_t)t * NN * 64,
            buf32 + OFF_WH + (size_t)t * 64 * NC,
            buf32 + OFF_WL + (size_t)t * 64 * NC, NC,
            buf + OFF_BCAT + t * NC,
            buf32 + (t ? OFF_C1 : OFF_C0), NCW, NN);
    }

    // 3) single edge pass (all 4 relations; f16x2 numerator RED)
    dim3 gE((EE + 7) / 8, 4);
    edge_pass<<<gE, 256>>>(rel_pri, s0, d0, s1, d1, s2, d2, s3, d3);

    // 4) normalize + mean -> packed AGG images
    agg_pack<<<2048, 256>>>();

    // 5) output projection [NN,128] x [128,128] per type (fp32 out)
    for (int t = 0; t < 2; t++) {
        dim3 gg(mblocks, 128 / BN);
        gemm3<false><<<gg, 256, GSMEM_BYTES>>>(
            buf32 + OFF_AGGH + (size_t)t * NN * 64,
            buf32 + OFF_AGGL + (size_t)t * NN * 64,
            buf32 + OFF_WAH + (size_t)t * 64 * 128,
            buf32 + OFF_WAL + (size_t)t * 64 * 128, 128,
            ba + t * 128,
            (uint32_t*)(buf + OFF_TRANS + (size_t)t * NN * 128), 128, NN);
    }

    // 6) skip + layernorm -> out
    ln_kernel<<<(2 * NN * 32 + 255) / 256, 256>>>(h0, h1, skip, ln_g, ln_b, (float*)d_out);
}

// round 17
// speedup vs baseline: 1.1019x; 1.0515x over previous
#include <cuda_runtime.h>
#include <cuda_bf16.h>
#include <cuda_fp16.h>
#include <cstdint>
#include <math.h>

// ---------------------------------------------------------------------------
// Problem constants
// ---------------------------------------------------------------------------
#define NN 50000      // nodes per type
#define EE 200000     // edges per relation
// REL = [(0,1),(1,0),(0,0),(1,1)]
#define NC 640        // fused projection width: [K_rA | K_rB | V_rA | V_rB | Q]
#define NCW 320       // bf16-packed row width in 32-bit words

// ---------------------------------------------------------------------------
// Scratch layout (32-bit words)
// ---------------------------------------------------------------------------
constexpr size_t OFF_C0    = 0;                                  // NN*320 (bf16x2)
constexpr size_t OFF_C1    = OFF_C0    + (size_t)NN * NCW;
constexpr size_t OFF_N16   = OFF_C1    + (size_t)NN * NCW;       // 4*NN*64 (f16x2 words)
constexpr size_t OFF_DEN   = OFF_N16   + (size_t)4 * NN * 64;    // 4*NN*8 fp32
constexpr size_t OFF_TRANS = OFF_DEN   + (size_t)4 * NN * 8;     // 2*NN*128 fp32
constexpr size_t OFF_AGGH  = OFF_TRANS + (size_t)2 * NN * 128;   // 2*NN*64 bf16x2
constexpr size_t OFF_AGGL  = OFF_AGGH  + (size_t)2 * NN * 64;
constexpr size_t OFF_XH    = OFF_AGGL  + (size_t)2 * NN * 64;    // 2*NN*64
constexpr size_t OFF_XL    = OFF_XH    + (size_t)2 * NN * 64;
constexpr size_t OFF_BCAT  = OFF_XL    + (size_t)2 * NN * 64;    // 2*640 fp32
constexpr size_t OFF_WH    = OFF_BCAT  + (size_t)2 * NC;         // 2*64*640
constexpr size_t OFF_WL    = OFF_WH    + (size_t)2 * 64 * NC;
constexpr size_t OFF_WAH   = OFF_WL    + (size_t)2 * 64 * NC;    // 2*64*128
constexpr size_t OFF_WAL   = OFF_WAH   + (size_t)2 * 64 * 128;
constexpr size_t BUF_TOTAL = OFF_WAL   + (size_t)2 * 64 * 128;

__device__ float g_buf[BUF_TOTAL];

// ---------------------------------------------------------------------------
// helpers
// ---------------------------------------------------------------------------
__device__ __forceinline__ uint32_t pack_bf16x2(float x, float y) {
    uint32_t r;
    asm("cvt.rn.bf16x2.f32 %0, %1, %2;" : "=r"(r) : "f"(y), "f"(x));
    return r;
}
__device__ __forceinline__ uint32_t pack_f16x2(float x, float y) {
    uint32_t r;
    asm("cvt.rn.f16x2.f32 %0, %1, %2;" : "=r"(r) : "f"(y), "f"(x));
    return r;
}
__device__ __forceinline__ float lo_as_f32(uint32_t p) { return __uint_as_float(p << 16); }
__device__ __forceinline__ float hi_as_f32(uint32_t p) { return __uint_as_float(p & 0xffff0000u); }

__device__ __forceinline__ void mma_bf16(float* c, const uint32_t* a, const uint32_t* b) {
    asm volatile(
        "mma.sync.aligned.m16n8k16.row.col.f32.bf16.bf16.f32 "
        "{%0,%1,%2,%3}, {%4,%5,%6,%7}, {%8,%9}, {%0,%1,%2,%3};"
        : "+f"(c[0]), "+f"(c[1]), "+f"(c[2]), "+f"(c[3])
        : "r"(a[0]), "r"(a[1]), "r"(a[2]), "r"(a[3]), "r"(b[0]), "r"(b[1]));
}

__device__ __forceinline__ void ldsm_x4(uint32_t* r, uint32_t addr) {
    asm volatile("ldmatrix.sync.aligned.m8n8.x4.shared.b16 {%0,%1,%2,%3}, [%4];"
                 : "=r"(r[0]), "=r"(r[1]), "=r"(r[2]), "=r"(r[3]) : "r"(addr));
}

__device__ __forceinline__ void cp_async16(uint32_t dst, const void* src, int srcbytes) {
    asm volatile("cp.async.cg.shared.global [%0], [%1], 16, %2;"
                 :: "r"(dst), "l"(src), "r"(srcbytes) : "memory");
}

__host__ __device__ __forceinline__ int wperm(int n) {
    return (n & ~63) | (((n & 7) << 3) | ((n >> 3) & 7));
}

// ---------------------------------------------------------------------------
// 3xBF16 tensor-core GEMM. launch_bounds(256,3). gridDim.z selects the node
// type; per-type strides are passed so both types run in ONE launch.
// ---------------------------------------------------------------------------
#define BM 128
#define BN 64
#define APITCH 20
#define A_STG (BM * APITCH)
#define W_STG (16 * 72)
#define GSMEM_WORDS (4 * A_STG + 4 * W_STG)
#define GSMEM_BYTES (GSMEM_WORDS * 4)

template<bool OUT_BF16>
__global__ __launch_bounds__(256, 3) void gemm3(const uint32_t* __restrict__ AH,
                                                const uint32_t* __restrict__ AL,
                                                const uint32_t* __restrict__ WH,
                                                const uint32_t* __restrict__ WL,
                                                int ldww,
                                                const float* __restrict__ bias,
                                                uint32_t* __restrict__ Cw, int ldcw,
                                                int M,
                                                size_t tsA, size_t tsW, int tsB, size_t tsC) {
    extern __shared__ uint32_t sm[];
    uint32_t smbase = (uint32_t)__cvta_generic_to_shared(sm);

    int z = blockIdx.z;
    AH += (size_t)z * tsA;
    AL += (size_t)z * tsA;
    WH += (size_t)z * tsW;
    WL += (size_t)z * tsW;
    bias += z * tsB;
    Cw += (size_t)z * tsC;

    int tid  = threadIdx.x;
    int warp = tid >> 5;
    int lane = tid & 31;
    int g    = lane >> 2;
    int t4   = lane & 3;
    int warpM = warp >> 1;
    int warpN = warp & 1;

    int m0 = blockIdx.x * BM;
    int n0 = blockIdx.y * BN;

    int lrow  = lane & 15;
    int lcolw = (lane >> 4) * 4;

    float acc[2][4][4];
#pragma unroll
    for (int i = 0; i < 2; i++)
#pragma unroll
        for (int j = 0; j < 4; j++)
#pragma unroll
            for (int k = 0; k < 4; k++) acc[i][j][k] = 0.f;

    auto stage_load = [&](int s, int kb) {
        int kb2 = kb >> 1;
#pragma unroll
        for (int i = 0; i < 2; i++) {
            int c   = i * 256 + tid;
            int row = c >> 2;
            int cw  = (c & 3) * 4;
            int m   = m0 + row;
            int ok  = (m < M) ? 16 : 0;
            size_t srcoff = (size_t)(m < M ? m : M - 1) * 64 + kb2 + cw;
            uint32_t dH = smbase + (uint32_t)((s * A_STG + row * APITCH + cw) * 4);
            uint32_t dL = smbase + (uint32_t)(((2 + s) * A_STG + row * APITCH + cw) * 4);
            cp_async16(dH, AH + srcoff, ok);
            cp_async16(dL, AL + srcoff, ok);
        }
        {
            int pk = tid >> 4;
            int cg = tid & 15;
            size_t srcoff = (size_t)(kb2 + pk) * ldww + n0 + cg * 4;
            uint32_t dH = smbase + (uint32_t)((4 * A_STG + s * W_STG + pk * 72 + cg * 4) * 4);
            uint32_t dL = smbase + (uint32_t)((4 * A_STG + (2 + s) * W_STG + pk * 72 + cg * 4) * 4);
            cp_async16(dH, WH + srcoff, 16);
            cp_async16(dL, WL + srcoff, 16);
        }
        asm volatile("cp.async.commit_group;" ::: "memory");
    };

    stage_load(0, 0);

    int s = 0;
    for (int kb = 0; kb < 128; kb += 32, s ^= 1) {
        if (kb + 32 < 128) {
            stage_load(s ^ 1, kb + 32);
            asm volatile("cp.async.wait_group 1;" ::: "memory");
        } else {
            asm volatile("cp.async.wait_group 0;" ::: "memory");
        }
        __syncthreads();

        uint32_t asHs = smbase + (uint32_t)(s * A_STG * 4);
        uint32_t asLs = smbase + (uint32_t)((2 + s) * A_STG * 4);
        const uint32_t* wsH = sm + 4 * A_STG + s * W_STG;
        const uint32_t* wsL = sm + 4 * A_STG + (2 + s) * W_STG;

#pragma unroll
        for (int ks = 0; ks < 2; ks++) {
            int kp = ks * 8;
            uint32_t ah[2][4], al[2][4];
#pragma unroll
            for (int mt = 0; mt < 2; mt++) {
                int rb = warpM * 32 + mt * 16;
                uint32_t off = (uint32_t)(((rb + lrow) * APITCH + kp + lcolw) * 4);
                ldsm_x4(ah[mt], asHs + off);
                ldsm_x4(al[mt], asLs + off);
            }
            int colw = g * 8 + warpN * 4;
            uint4 bh0 = *(const uint4*)&wsH[(kp + t4) * 72 + colw];
            uint4 bh1 = *(const uint4*)&wsH[(kp + t4 + 4) * 72 + colw];
            uint4 bl0 = *(const uint4*)&wsL[(kp + t4) * 72 + colw];
            uint4 bl1 = *(const uint4*)&wsL[(kp + t4 + 4) * 72 + colw];
            const uint32_t* ph0 = (const uint32_t*)&bh0;
            const uint32_t* ph1 = (const uint32_t*)&bh1;
            const uint32_t* pl0 = (const uint32_t*)&bl0;
            const uint32_t* pl1 = (const uint32_t*)&bl1;
#pragma unroll
            for (int nt = 0; nt < 4; nt++) {
                uint32_t bh[2] = {ph0[nt], ph1[nt]};
                uint32_t bl[2] = {pl0[nt], pl1[nt]};
#pragma unroll
                for (int mt = 0; mt < 2; mt++) {
                    mma_bf16(acc[mt][nt], ah[mt], bh);
                    mma_bf16(acc[mt][nt], ah[mt], bl);
                    mma_bf16(acc[mt][nt], al[mt], bh);
                }
            }
        }
        __syncthreads();
    }

#pragma unroll
    for (int mt = 0; mt < 2; mt++) {
#pragma unroll
        for (int nt = 0; nt < 4; nt++) {
            int col = n0 + warpN * 32 + nt * 8 + t4 * 2;
            float b0 = bias[col], b1 = bias[col + 1];
            int r0 = m0 + warpM * 32 + mt * 16 + g;
            int r1 = r0 + 8;
            if (OUT_BF16) {
                if (r0 < M)
                    Cw[(size_t)r0 * ldcw + (col >> 1)] = pack_bf16x2(acc[mt][nt][0] + b0, acc[mt][nt][1] + b1);
                if (r1 < M)
                    Cw[(size_t)r1 * ldcw + (col >> 1)] = pack_bf16x2(acc[mt][nt][2] + b0, acc[mt][nt][3] + b1);
            } else {
                float* C = (float*)Cw;
                if (r0 < M) {
                    float2 v = make_float2(acc[mt][nt][0] + b0, acc[mt][nt][1] + b1);
                    *(float2*)&C[(size_t)r0 * ldcw + col] = v;
                }
                if (r1 < M) {
                    float2 v = make_float2(acc[mt][nt][2] + b0, acc[mt][nt][3] + b1);
                    *(float2*)&C[(size_t)r1 * ldcw + col] = v;
                }
            }
        }
    }
}

// ---------------------------------------------------------------------------
// Fused weight prep: computes the rel_att/rel_msg fold on the fly and writes
// the packed+permuted bf16 hi/lo weight images and fused biases directly.
// ---------------------------------------------------------------------------
__device__ __forceinline__ float wcat_val(int t, int i, int c,
                                          const float* Wk, const float* Wq, const float* Wv,
                                          const float* rel_att, const float* rel_msg) {
    if (c < 512) {
        int sel = c >> 7;
        int rel = (sel & 1) ? (t == 0 ? 2 : 3) : (t == 0 ? 0 : 1);
        int isV = sel >> 1;
        int o = c & 127, h = o >> 4, eo = o & 15;
        const float* Wsrc = (isV ? Wv : Wk) + (size_t)t * 16384 + (size_t)i * 128 + h * 16;
        const float* R = (isV ? rel_msg : rel_att) + (((size_t)rel * 8 + h) * 16) * 16 + eo;
        float a = 0.f;
#pragma unroll
        for (int d = 0; d < 16; d++) a += Wsrc[d] * R[d * 16];
        return a;
    }
    return Wq[(size_t)t * 16384 + (size_t)i * 128 + (c - 512)];
}

__global__ void setup_weights(const float* __restrict__ Wk, const float* __restrict__ bk,
                              const float* __restrict__ Wq, const float* __restrict__ bq,
                              const float* __restrict__ Wv, const float* __restrict__ bv,
                              const float* __restrict__ Wa,
                              const float* __restrict__ rel_att, const float* __restrict__ rel_msg) {
    uint32_t* W32 = (uint32_t*)g_buf;
    int idx = blockIdx.x * blockDim.x + threadIdx.x;
    int n_cat = 2 * 64 * NC;
    int n_wa  = 2 * 64 * 128;
    if (idx < n_cat) {
        int t  = idx / (64 * NC);
        int pk = (idx / NC) & 63;
        int n  = idx % NC;
        float w0 = wcat_val(t, 2 * pk,     n, Wk, Wq, Wv, rel_att, rel_msg);
        float w1 = wcat_val(t, 2 * pk + 1, n, Wk, Wq, Wv, rel_att, rel_msg);
        uint32_t h = pack_bf16x2(w0, w1);
        uint32_t l = pack_bf16x2(w0 - lo_as_f32(h), w1 - hi_as_f32(h));
        int p = wperm(n);
        W32[OFF_WH + (size_t)t * 64 * NC + (size_t)pk * NC + p] = h;
        W32[OFF_WL + (size_t)t * 64 * NC + (size_t)pk * NC + p] = l;
        if (pk == 0) {
            float bval;
            if (n < 512) {
                int sel = n >> 7;
                int rel = (sel & 1) ? (t == 0 ? 2 : 3) : (t == 0 ? 0 : 1);
                int isV = sel >> 1;
                int o = n & 127, hh = o >> 4, eo = o & 15;
                const float* bsrc = (isV ? bv : bk) + t * 128 + hh * 16;
                const float* R = (isV ? rel_msg : rel_att) + (((size_t)rel * 8 + hh) * 16) * 16 + eo;
                float b = 0.f;
#pragma unroll
                for (int d = 0; d < 16; d++) b += bsrc[d] * R[d * 16];
                bval = b;
            } else {
                bval = bq[t * 128 + (n - 512)];
            }
            g_buf[OFF_BCAT + t * NC + n] = bval;
        }
    } else if (idx < n_cat + n_wa) {
        int j  = idx - n_cat;
        int t  = j / (64 * 128);
        int pk = (j / 128) & 63;
        int n  = j % 128;
        float w0 = Wa[(size_t)t * 16384 + (size_t)(2 * pk)     * 128 + n];
        float w1 = Wa[(size_t)t * 16384 + (size_t)(2 * pk + 1) * 128 + n];
        uint32_t h = pack_bf16x2(w0, w1);
        uint32_t l = pack_bf16x2(w0 - lo_as_f32(h), w1 - hi_as_f32(h));
        int p = wperm(n);
        W32[OFF_WAH + (size_t)t * 64 * 128 + (size_t)pk * 128 + p] = h;
        W32[OFF_WAL + (size_t)t * 64 * 128 + (size_t)pk * 128 + p] = l;
    }
}

// ---------------------------------------------------------------------------
// Fused data setup: pack node features to bf16 hi/lo images AND zero the
// N16/DEN accumulator region.
// ---------------------------------------------------------------------------
__global__ void setup_data(const float* __restrict__ h0, const float* __restrict__ h1) {
    uint32_t* W32 = (uint32_t*)g_buf;
    size_t gid = (size_t)blockIdx.x * blockDim.x + threadIdx.x;
    size_t stride = (size_t)gridDim.x * blockDim.x;

    size_t totalx = (size_t)2 * NN * 64;
    for (size_t idx = gid; idx < totalx; idx += stride) {
        int t = (int)(idx / (NN * 64));
        size_t rem = idx - (size_t)t * (NN * 64);
        const float* h = t ? h1 : h0;
        float2 v = *(const float2*)&h[rem * 2];
        uint32_t hi = pack_bf16x2(v.x, v.y);
        uint32_t lo = pack_bf16x2(v.x - lo_as_f32(hi), v.y - hi_as_f32(hi));
        W32[OFF_XH + (size_t)t * NN * 64 + rem] = hi;
        W32[OFF_XL + (size_t)t * NN * 64 + rem] = lo;
    }

    uint4* p = (uint4*)(g_buf + OFF_N16);
    size_t n4 = ((size_t)4 * NN * 64 + (size_t)4 * NN * 8) / 4;
    uint4 z = make_uint4(0, 0, 0, 0);
    for (size_t i = gid; i < n4; i += stride) p[i] = z;
}

// ---------------------------------------------------------------------------
// Single edge pass over bf16 projections. One warp per edge.
// Numerator accumulated via ONE red.v2.f16x2 per lane (1 msg, 2 word-RMWs).
// ---------------------------------------------------------------------------
__global__ void edge_pass(const float* __restrict__ pri,
                          const int* __restrict__ s0, const int* __restrict__ d0,
                          const int* __restrict__ s1, const int* __restrict__ d1,
                          const int* __restrict__ s2, const int* __restrict__ d2,
                          const int* __restrict__ s3, const int* __restrict__ d3) {
    int r = blockIdx.y;
    int e = blockIdx.x * (blockDim.x >> 5) + (threadIdx.x >> 5);
    if (e >= EE) return;
    int lane = threadIdx.x & 31;

    const int* src = (r == 0) ? s0 : (r == 1) ? s1 : (r == 2) ? s2 : s3;
    const int* dst = (r == 0) ? d0 : (r == 1) ? d1 : (r == 2) ? d2 : d3;
    int st = r & 1;
    int dt = (r == 0 || r == 3) ? 1 : 0;
    int sliceKVw = (r >> 1) * 64;

    int s = src[e];
    int d = dst[e];

    const uint32_t* Cw = (const uint32_t*)g_buf;
    const uint32_t* Cs = Cw + (st ? OFF_C1 : OFF_C0) + (size_t)s * NCW;
    const uint32_t* Cd = Cw + (dt ? OFF_C1 : OFF_C0) + (size_t)d * NCW;

    uint2 qw = *(const uint2*)&Cd[256 + lane * 2];
    uint2 kw = *(const uint2*)&Cs[sliceKVw + lane * 2];
    float p = lo_as_f32(qw.x) * lo_as_f32(kw.x) + hi_as_f32(qw.x) * hi_as_f32(kw.x)
            + lo_as_f32(qw.y) * lo_as_f32(kw.y) + hi_as_f32(qw.y) * hi_as_f32(kw.y);
    p += __shfl_xor_sync(0xffffffffu, p, 1);
    p += __shfl_xor_sync(0xffffffffu, p, 2);
    int h = lane >> 2;
    float sc = p * pri[r * 8 + h] * 0.25f;
    float ex = __expf(sc);

    if ((lane & 3) == 0) {
        float* dp = g_buf + OFF_DEN + ((size_t)r * NN + d) * 8 + h;
        asm volatile("red.global.add.f32 [%0], %1;" :: "l"(dp), "f"(ex) : "memory");
    }

    uint2 vw = *(const uint2*)&Cs[128 + sliceKVw + lane * 2];
    float p0 = lo_as_f32(vw.x) * ex, p1 = hi_as_f32(vw.x) * ex;
    float p2 = lo_as_f32(vw.y) * ex, p3 = hi_as_f32(vw.y) * ex;
    uint32_t w0 = pack_f16x2(p0, p1);
    uint32_t w1 = pack_f16x2(p2, p3);
    uint32_t* np = (uint32_t*)g_buf + OFF_N16 + ((size_t)r * NN + d) * 64 + lane * 2;
    asm volatile("red.global.add.noftz.v2.f16x2 [%0], {%1,%2};"
                 :: "l"(np), "r"(w0), "r"(w1) : "memory");
}

// ---------------------------------------------------------------------------
// Normalize + cross-relation mean; reads f16x2 numerator; emits packed bf16
// hi/lo AGG images
// ---------------------------------------------------------------------------
__global__ void agg_pack() {
    uint32_t* W32 = (uint32_t*)g_buf;
    const uint32_t* N16 = (const uint32_t*)g_buf + OFF_N16;
    size_t total = (size_t)2 * NN * 64;
    size_t i = (size_t)blockIdx.x * blockDim.x + threadIdx.x;
    size_t stride = (size_t)gridDim.x * blockDim.x;
    for (; i < total; i += stride) {
        int w = (int)(i & 63);
        size_t nt = i >> 6;
        int t = (int)(nt / NN);
        int n = (int)(nt % NN);
        int rA = (t == 0) ? 1 : 0;
        int rB = (t == 0) ? 2 : 3;
        int h = w >> 3;
        float dA = g_buf[OFF_DEN + ((size_t)rA * NN + n) * 8 + h];
        float dB = g_buf[OFF_DEN + ((size_t)rB * NN + n) * 8 + h];
        float iA = (dA > 0.f) ? 0.5f / dA : 0.f;
        float iB = (dB > 0.f) ? 0.5f / dB : 0.f;
        uint32_t wA = N16[((size_t)rA * NN + n) * 64 + w];
        uint32_t wB = N16[((size_t)rB * NN + n) * 64 + w];
        float2 fA = __half22float2(*(const __half2*)&wA);
        float2 fB = __half22float2(*(const __half2*)&wB);
        float a0 = fA.x * iA + fB.x * iB;
        float a1 = fA.y * iA + fB.y * iB;
        uint32_t hi = pack_bf16x2(a0, a1);
        uint32_t lo = pack_bf16x2(a0 - lo_as_f32(hi), a1 - hi_as_f32(hi));
        W32[OFF_AGGH + i] = hi;
        W32[OFF_AGGL + i] = lo;
    }
}

// ---------------------------------------------------------------------------
// Skip + LayerNorm. One warp per row.
// ---------------------------------------------------------------------------
__global__ void ln_kernel(const float* __restrict__ h0, const float* __restrict__ h1,
                          const float* __restrict__ skip,
                          const float* __restrict__ ln_g, const float* __restrict__ ln_b,
                          float* __restrict__ out) {
    int warp = (blockIdx.x * blockDim.x + threadIdx.x) >> 5;
    int lane = threadIdx.x & 31;
    if (warp >= 2 * NN) return;
    int t = warp / NN;
    int n = warp % NN;

    const float* hh = (t == 0) ? h0 : h1;
    const float* tr = g_buf + OFF_TRANS + ((size_t)t * NN + n) * 128;
    float alpha = 1.f / (1.f + __expf(-skip[t]));
    float beta = 1.f - alpha;

    float4 tv = *(const float4*)&tr[lane * 4];
    float4 hv = *(const float4*)&hh[(size_t)n * 128 + lane * 4];
    float4 x;
    x.x = tv.x * alpha + hv.x * beta;
    x.y = tv.y * alpha + hv.y * beta;
    x.z = tv.z * alpha + hv.z * beta;
    x.w = tv.w * alpha + hv.w * beta;

    float s1 = x.x + x.y + x.z + x.w;
    float s2 = x.x * x.x + x.y * x.y + x.z * x.z + x.w * x.w;
#pragma unroll
    for (int o = 16; o >= 1; o >>= 1) {
        s1 += __shfl_xor_sync(0xffffffffu, s1, o);
        s2 += __shfl_xor_sync(0xffffffffu, s2, o);
    }
    float mean = s1 * (1.f / 128.f);
    float var  = s2 * (1.f / 128.f) - mean * mean;
    float rstd = rsqrtf(var + 1e-5f);

    int j = lane * 4;
    float4 g4 = *(const float4*)&ln_g[t * 128 + j];
    float4 b4 = *(const float4*)&ln_b[t * 128 + j];
    float4 o4;
    o4.x = (x.x - mean) * rstd * g4.x + b4.x;
    o4.y = (x.y - mean) * rstd * g4.y + b4.y;
    o4.z = (x.z - mean) * rstd * g4.z + b4.z;
    o4.w = (x.w - mean) * rstd * g4.w + b4.w;
    *(float4*)&out[((size_t)t * NN + n) * 128 + j] = o4;
}

// ---------------------------------------------------------------------------
// Host launcher
// ---------------------------------------------------------------------------
extern "C" void kernel_launch(void* const* d_in, const int* in_sizes, int n_in,
                              void* d_out, int out_size) {
    const float* h0 = (const float*)d_in[0];
    const float* h1 = (const float*)d_in[1];
    const int* s0 = (const int*)d_in[2];
    const int* d0 = (const int*)d_in[3];
    const int* s1 = (const int*)d_in[4];
    const int* d1 = (const int*)d_in[5];
    const int* s2 = (const int*)d_in[6];
    const int* d2 = (const int*)d_in[7];
    const int* s3 = (const int*)d_in[8];
    const int* d3 = (const int*)d_in[9];
    const float* Wk = (const float*)d_in[10];
    const float* bk = (const float*)d_in[11];
    const float* Wq = (const float*)d_in[12];
    const float* bq = (const float*)d_in[13];
    const float* Wv = (const float*)d_in[14];
    const float* bv = (const float*)d_in[15];
    const float* Wa = (const float*)d_in[16];
    const float* ba = (const float*)d_in[17];
    const float* rel_att = (const float*)d_in[18];
    const float* rel_msg = (const float*)d_in[19];
    const float* rel_pri = (const float*)d_in[20];
    const float* skip = (const float*)d_in[21];
    const float* ln_g = (const float*)d_in[22];
    const float* ln_b = (const float*)d_in[23];

    static float* buf = nullptr;
    if (!buf) {
        cudaGetSymbolAddress((void**)&buf, g_buf);
        cudaFuncSetAttribute(gemm3<true>,  cudaFuncAttributeMaxDynamicSharedMemorySize, GSMEM_BYTES);
        cudaFuncSetAttribute(gemm3<false>, cudaFuncAttributeMaxDynamicSharedMemorySize, GSMEM_BYTES);
    }
    uint32_t* buf32 = (uint32_t*)buf;

    // 1) fused setup: weights (fold+pack) and data (feature pack + accum zero)
    setup_weights<<<(2 * 64 * NC + 2 * 64 * 128 + 255) / 256, 256>>>(
        Wk, bk, Wq, bq, Wv, bv, Wa, rel_att, rel_msg);
    setup_data<<<2048, 256>>>(h0, h1);

    // 2) fused KVQ projections: both types in one launch (gridDim.z = 2)
    int mblocks = (NN + BM - 1) / BM;
    {
        dim3 gg(mblocks, NC / BN, 2);
        gemm3<true><<<gg, 256, GSMEM_BYTES>>>(
            buf32 + OFF_XH, buf32 + OFF_XL,
            buf32 + OFF_WH, buf32 + OFF_WL, NC,
            buf + OFF_BCAT,
            buf32 + OFF_C0, NCW, NN,
            (size_t)NN * 64, (size_t)64 * NC, NC, (size_t)NN * NCW);
    }

    // 3) single edge pass (all 4 relations; v2.f16x2 numerator RED)
    dim3 gE((EE + 7) / 8, 4);
    edge_pass<<<gE, 256>>>(rel_pri, s0, d0, s1, d1, s2, d2, s3, d3);

    // 4) normalize + mean -> packed AGG images
    agg_pack<<<2048, 256>>>();

    // 5) output projection, both types in one launch (fp32 out)
    {
        dim3 gg(mblocks, 128 / BN, 2);
        gemm3<false><<<gg, 256, GSMEM_BYTES>>>(
            buf32 + OFF_AGGH, buf32 + OFF_AGGL,
            buf32 + OFF_WAH, buf32 + OFF_WAL, 128,
            ba,
            (uint32_t*)(buf + OFF_TRANS), 128, NN,
            (size_t)NN * 64, (size_t)64 * 128, 128, (size_t)NN * 128);
    }

    // 6) skip + layernorm -> out
    ln_kernel<<<(2 * NN * 32 + 255) / 256, 256>>>(h0, h1, skip, ln_g, ln_b, (float*)d_out);
}